// round 4
// baseline (speedup 1.0000x reference)
#include <cuda_runtime.h>
#include <cuda_bf16.h>
#include <math.h>
#include <stdint.h>

#define NE 640000
#define NN 20000
#define NG 16

// ---- device scratch (no allocations allowed) ----
__device__ float g_sh [(size_t)NE * 16];
__device__ float g_emb[(size_t)NE * 10];
__device__ float g_h  [(size_t)NE * 256];
__device__ float g_w1 [(size_t)NE * 272];
__device__ float g_w2 [(size_t)NE * 32];
__device__ float g_x0 [(size_t)NN * 16];
__device__ float g_x1 [(size_t)NN * 160];
__device__ float g_gate[(size_t)NN * 128];
__device__ float g_nodeout[NN];
__device__ float g_cg[651];

// CG table offsets, layout (i*d2+j)*d3+k
#define OFF000 0
#define OFF110 1
#define OFF220 10
#define OFF330 35
#define OFF011 84
#define OFF101 93
#define OFF111 102
#define OFF121 129
#define OFF211 174
#define OFF221 219
#define OFF231 294
#define OFF321 399
#define OFF331 504
#define CGTOT  651

#define INV_NN     0.17677669529663687f   // 1/sqrt(E/N)=1/sqrt(32)
#define FCH_SCALE  0.02795084971874737f   // sqrt(2/10)/16
#define ALPHA_S    0.5f
#define ALPHA_V6   0.7071067811865476f
#define ALPHA_TP2  0.17677669529663687f   // sqrt(1/32)
#define INV_SQRT_N 0.007071067811865475f  // 1/sqrt(20000)

#define SQ3f   1.7320508075688772f
#define SQ5f   2.23606797749979f
#define SQ7f   2.6457513110645907f
#define SQ15f  3.872983346207417f
#define SQ42f  6.48074069840786f
#define SQ70f  8.366600265340756f
#define SQ105f 10.246950765959598f
#define SQRT10f 3.1622776601683795f

// ============================================================================
// CG init (mirrors reference exactly, fp64)
// ============================================================================
__device__ double dfact(int n){ double r=1.0; for(int i=2;i<=n;i++) r*= (double)i; return r; }

__device__ double cg_complex_d(int j1,int m1,int j2,int m2,int j3,int m3){
    if (m1+m2 != m3) return 0.0;
    double pref = sqrt((2.0*j3+1.0)*dfact(j3+j1-j2)*dfact(j3-j1+j2)*dfact(j1+j2-j3)/dfact(j1+j2+j3+1));
    pref *= sqrt(dfact(j3+m3)*dfact(j3-m3)*dfact(j1-m1)*dfact(j1+m1)*dfact(j2-m2)*dfact(j2+m2));
    double s = 0.0;
    for (int k=0; k<=j1+j2-j3; k++){
        int e2=j1-m1-k, e3=j2+m2-k, e4=j3-j2+m1+k, e5=j3-j1-m2+k;
        if (e2<0||e3<0||e4<0||e5<0) continue;
        double den = dfact(k)*dfact(j1+j2-j3-k)*dfact(e2)*dfact(e3)*dfact(e4)*dfact(e5);
        s += ((k&1)? -1.0:1.0)/den;
    }
    return pref*s;
}

__device__ void build_U(int l, double* Ur, double* Ui){
    int d = 2*l+1;
    for (int i=0;i<d*d;i++){ Ur[i]=0.0; Ui[i]=0.0; }
    Ur[l*d+l] = 1.0;
    const double is2 = 0.70710678118654752440;
    for (int m=1;m<=l;m++){
        double sgn = (m&1)? -1.0:1.0;
        Ur[(l+m)*d+(l+m)] = sgn*is2;
        Ur[(l+m)*d+(l-m)] = is2;
        Ui[(l-m)*d+(l+m)] = -sgn*is2;
        Ui[(l-m)*d+(l-m)] = is2;
    }
}

__global__ void cg_init_kernel(){
    const int L1[13]  = {0,1,2,3,0,1,1,1,2,2,2,3,3};
    const int L2[13]  = {0,1,2,3,1,0,1,2,1,2,3,2,3};
    const int L3[13]  = {0,0,0,0,1,1,1,1,1,1,1,1,1};
    const int OFF[14] = {0,1,10,35,84,93,102,129,174,219,294,399,504,651};
    __shared__ double sC[CGTOT], sTr[CGTOT], sTi[CGTOT];
    int tid = threadIdx.x;
    int combo = -1, r = 0;
    if (tid < CGTOT){
        for (int t=0;t<13;t++)
            if (tid >= OFF[t] && tid < OFF[t+1]) { combo=t; r=tid-OFF[t]; break; }
    }
    if (combo >= 0){
        int l1=L1[combo], l2=L2[combo], l3=L3[combo];
        int d2=2*l2+1, d3=2*l3+1;
        int c=r%d3, b=(r/d3)%d2, a=r/(d3*d2);
        sC[tid] = cg_complex_d(l1, a-l1, l2, b-l2, l3, c-l3);
    }
    __syncthreads();
    if (combo >= 0){
        int l1=L1[combo], l2=L2[combo], l3=L3[combo];
        int d1=2*l1+1, d2=2*l2+1, d3=2*l3+1;
        int k=r%d3, j=(r/d3)%d2, i=r/(d3*d2);
        double U1r[49],U1i[49],U2r[49],U2i[49],U3r[9],U3i[9];
        build_U(l1,U1r,U1i); build_U(l2,U2r,U2i); build_U(l3,U3r,U3i);
        double tr=0.0, ti=0.0;
        for (int a=0;a<d1;a++){
            double r1=U1r[i*d1+a], i1=U1i[i*d1+a];
            if (r1==0.0 && i1==0.0) continue;
            for (int b=0;b<d2;b++){
                double r2=U2r[j*d2+b], i2=U2i[j*d2+b];
                if (r2==0.0 && i2==0.0) continue;
                double pr=r1*r2-i1*i2, pi=r1*i2+i1*r2;
                for (int c=0;c<d3;c++){
                    double cv = sC[OFF[combo]+(a*d2+b)*d3+c];
                    if (cv==0.0) continue;
                    double r3=U3r[k*d3+c], i3=U3i[k*d3+c];
                    tr += (pr*r3 + pi*i3)*cv;   // * conj(U3)
                    ti += (pi*r3 - pr*i3)*cv;
                }
            }
        }
        sTr[tid]=tr; sTi[tid]=ti;
    }
    __syncthreads();
    if (tid < 13){
        int o0=OFF[tid], o1=OFF[tid+1];
        double sa=0.0, sb=0.0;
        for (int q=o0;q<o1;q++){ sa += fabs(sTr[q]); sb += fabs(sTi[q]); }
        bool useR = (sa >= sb);
        double nrm = 0.0;
        for (int q=o0;q<o1;q++){ double v = useR? sTr[q]:sTi[q]; nrm += v*v; }
        double inv = 1.0/sqrt(nrm);
        for (int q=o0;q<o1;q++){ double v = useR? sTr[q]:sTi[q]; g_cg[q] = (float)(v*inv); }
    }
}

// ============================================================================
__global__ void zero_kernel(float* __restrict__ dout){
    int i = blockIdx.x*blockDim.x + threadIdx.x;
    if (i < NN*16)  g_x0[i] = 0.f;
    if (i < NN*160) g_x1[i] = 0.f;
    if (i < NN)     g_nodeout[i] = 0.f;
    if (i < NG)     dout[i] = 0.f;
}

// ============================================================================
__global__ void edge_geom_kernel(const float* __restrict__ pos,
                                 const int* __restrict__ esrc,
                                 const int* __restrict__ edst){
    int e = blockIdx.x*blockDim.x + threadIdx.x;
    if (e >= NE) return;
    int s = esrc[e], d = edst[e];
    float ex = pos[d*3+0]-pos[s*3+0];
    float ey = pos[d*3+1]-pos[s*3+1];
    float ez = pos[d*3+2]-pos[s*3+2];
    float dn = sqrtf(ex*ex+ey*ey+ez*ez + 1e-12f);
    float inv = 1.f/dn;
    float x = ex*inv, y = ey*inv, z = ez*inv;
    float xx=x*x, yy=y*y, zz=z*z;
    float sh[16];
    sh[0]=1.f;
    sh[1]=SQ3f*y; sh[2]=SQ3f*z; sh[3]=SQ3f*x;
    sh[4]=SQ15f*x*y; sh[5]=SQ15f*y*z; sh[6]=0.5f*SQ5f*(3.f*zz-1.f);
    sh[7]=SQ15f*x*z; sh[8]=0.5f*SQ15f*(xx-yy);
    sh[9] =0.25f*SQ70f*y*(3.f*xx-yy);
    sh[10]=SQ105f*x*y*z;
    sh[11]=0.25f*SQ42f*y*(5.f*zz-1.f);
    sh[12]=0.5f*SQ7f*z*(5.f*zz-3.f);
    sh[13]=0.25f*SQ42f*x*(5.f*zz-1.f);
    sh[14]=0.5f*SQ105f*z*(xx-yy);
    sh[15]=0.25f*SQ70f*x*(xx-3.f*yy);

    float4* shp = reinterpret_cast<float4*>(g_sh + (size_t)e*16);
    shp[0]=make_float4(sh[0],sh[1],sh[2],sh[3]);
    shp[1]=make_float4(sh[4],sh[5],sh[6],sh[7]);
    shp[2]=make_float4(sh[8],sh[9],sh[10],sh[11]);
    shp[3]=make_float4(sh[12],sh[13],sh[14],sh[15]);

    const float step = 3.2f/11.f;
    #pragma unroll
    for (int i=0;i<10;i++){
        float c = (float)(i+1)*step;
        float u = (dn-c)/step;
        float u2 = u*u;
        float f = 0.f;
        if (u2 < 1.f){
            float den = fmaxf(1.f-u2, 1e-6f);
            f = 1.14136f*expf(-u2/den)*SQRT10f;
        }
        g_emb[(size_t)e*10+i] = f;
    }

    float* x0 = g_x0 + (size_t)d*16;
    #pragma unroll
    for (int i=0;i<16;i++) atomicAdd(x0+i, sh[i]*INV_NN);
}

// ============================================================================
// h = relu(emb @ Wfc) * sqrt(2/10)/16    (E x 10 @ 10 x 256)
// ============================================================================
__global__ void fch_kernel(const float* __restrict__ Wfc){
    __shared__ float es[320];          // 32 edges x 10 basis
    int e0 = blockIdx.x*32;
    int t = threadIdx.x;
    for (int i = t; i < 320; i += 256) es[i] = g_emb[(size_t)e0*10 + i];
    float wr[10];
    #pragma unroll
    for (int k=0;k<10;k++) wr[k] = Wfc[k*256 + t];
    __syncthreads();
    for (int el=0; el<32; el++){
        float acc = 0.f;
        #pragma unroll
        for (int k=0;k<10;k++) acc += es[el*10 + k]*wr[k];
        g_h[(size_t)(e0+el)*256 + t] = fmaxf(acc, 0.f)*FCH_SCALE;
    }
}

// ============================================================================
// C = g_h (E x 256) @ B (256 x N) ; N = 272 -> g_w1, N = 32 -> g_w2
// BM=64, BN=64, BK=16, 256 threads, 4x4 microtile
// ============================================================================
template<int N>
__global__ void sgemm_kernel(const float* __restrict__ B){
    float* C = (N == 272) ? g_w1 : g_w2;
    const float* A = g_h;
    __shared__ float As[16][65];
    __shared__ float Bs[16][64];
    int m0 = blockIdx.x*64, n0 = blockIdx.y*64;
    int t = threadIdx.x;
    int tx = t & 15, ty = t >> 4;
    int arow = t >> 2, acol = (t & 3)*4;
    int brow = t >> 4, bcol = (t & 15)*4;
    float acc[4][4] = {};
    for (int k0=0; k0<256; k0+=16){
        float4 av = *reinterpret_cast<const float4*>(A + (size_t)(m0+arow)*256 + k0 + acol);
        As[acol+0][arow]=av.x; As[acol+1][arow]=av.y; As[acol+2][arow]=av.z; As[acol+3][arow]=av.w;
        float4 bv = make_float4(0.f,0.f,0.f,0.f);
        if (n0 + bcol < N)
            bv = *reinterpret_cast<const float4*>(B + (size_t)(k0+brow)*N + n0 + bcol);
        *reinterpret_cast<float4*>(&Bs[brow][bcol]) = bv;
        __syncthreads();
        #pragma unroll
        for (int k=0;k<16;k++){
            float a0=As[k][ty*4+0], a1=As[k][ty*4+1], a2=As[k][ty*4+2], a3=As[k][ty*4+3];
            float b0=Bs[k][tx*4+0], b1=Bs[k][tx*4+1], b2=Bs[k][tx*4+2], b3=Bs[k][tx*4+3];
            acc[0][0]+=a0*b0; acc[0][1]+=a0*b1; acc[0][2]+=a0*b2; acc[0][3]+=a0*b3;
            acc[1][0]+=a1*b0; acc[1][1]+=a1*b1; acc[1][2]+=a1*b2; acc[1][3]+=a1*b3;
            acc[2][0]+=a2*b0; acc[2][1]+=a2*b1; acc[2][2]+=a2*b2; acc[2][3]+=a2*b3;
            acc[3][0]+=a3*b0; acc[3][1]+=a3*b1; acc[3][2]+=a3*b2; acc[3][3]+=a3*b3;
        }
        __syncthreads();
    }
    int col = n0 + tx*4;
    if (col < N){
        #pragma unroll
        for (int i=0;i<4;i++){
            float4 v = make_float4(acc[i][0],acc[i][1],acc[i][2],acc[i][3]);
            *reinterpret_cast<float4*>(C + (size_t)(m0+ty*4+i)*N + col) = v;
        }
    }
}

// ============================================================================
// TP1: per edge, 21 paths, scatter into g_x1[dst]
// ============================================================================
template<int D1,int D2>
__device__ __forceinline__ void contr3(const float* a, const float* b,
                                       const float* cgt, float* o){
    o[0]=0.f; o[1]=0.f; o[2]=0.f;
    #pragma unroll
    for (int i=0;i<D1;i++){
        #pragma unroll
        for (int j=0;j<D2;j++){
            float p = a[i]*b[j];
            const float* c = cgt + (i*D2+j)*3;
            o[0] += p*c[0]; o[1] += p*c[1]; o[2] += p*c[2];
        }
    }
}

__global__ void tp1_kernel(const int* __restrict__ esrc, const int* __restrict__ edst){
    __shared__ float cg[CGTOT];
    for (int i=threadIdx.x; i<CGTOT; i+=blockDim.x) cg[i] = g_cg[i];
    __syncthreads();
    int e = blockIdx.x*blockDim.x + threadIdx.x;
    if (e >= NE) return;
    int s = esrc[e], d = edst[e];
    float a[16], b[16];
    const float* xp = g_x0 + (size_t)s*16;
    #pragma unroll
    for (int i=0;i<16;i++) a[i] = xp[i];
    const float4* shp = reinterpret_cast<const float4*>(g_sh + (size_t)e*16);
    #pragma unroll
    for (int i=0;i<4;i++){ float4 v = shp[i]; b[i*4]=v.x; b[i*4+1]=v.y; b[i*4+2]=v.z; b[i*4+3]=v.w; }
    const float* w = g_w1 + (size_t)e*272;

    // scalar contractions (l,l,0)
    float s0 = a[0]*b[0]*cg[OFF000];
    float s1 = 0.f;
    #pragma unroll
    for (int i=0;i<3;i++){ float ai=a[1+i];
        #pragma unroll
        for (int j=0;j<3;j++) s1 += ai*b[1+j]*cg[OFF110+i*3+j]; }
    float s2 = 0.f;
    #pragma unroll
    for (int i=0;i<5;i++){ float ai=a[4+i];
        #pragma unroll
        for (int j=0;j<5;j++) s2 += ai*b[4+j]*cg[OFF220+i*5+j]; }
    float s3 = 0.f;
    #pragma unroll
    for (int i=0;i<7;i++){ float ai=a[9+i];
        #pragma unroll
        for (int j=0;j<7;j++) s3 += ai*b[9+j]*cg[OFF330+i*7+j]; }

    // vector contractions (l1,l2,1)
    float c01[3],c10[3],c12[3],c21[3],c23[3],c32[3],c11[3],c22[3],c33[3];
    contr3<1,3>(a+0, b+1, cg+OFF011, c01);
    contr3<3,1>(a+1, b+0, cg+OFF101, c10);
    contr3<3,5>(a+1, b+4, cg+OFF121, c12);
    contr3<5,3>(a+4, b+1, cg+OFF211, c21);
    contr3<5,7>(a+4, b+9, cg+OFF231, c23);
    contr3<7,5>(a+9, b+4, cg+OFF321, c32);
    contr3<3,3>(a+1, b+1, cg+OFF111, c11);
    contr3<5,5>(a+4, b+4, cg+OFF221, c22);
    contr3<7,7>(a+9, b+9, cg+OFF331, c33);

    float* dst = g_x1 + (size_t)d*160;
    // i3=0 (16 even scalars, out ch 0..15)
    #pragma unroll
    for (int c=0;c<16;c++){
        float v = ALPHA_S*(w[c]*s0 + w[64+c]*s1 + w[144+c]*s2 + w[224+c]*s3);
        atomicAdd(dst + c, v*INV_NN);
    }
    // i3=2 (ch 32..39), i3=4 (ch 48..55)
    #pragma unroll
    for (int c=0;c<8;c++){
        float v = ALPHA_S*(w[16+c]*s0 + w[80+c]*s1 + w[160+c]*s2 + w[240+c]*s3);
        atomicAdd(dst + 32 + c, v*INV_NN);
        float v2 = ALPHA_S*(w[24+c]*s0 + w[88+c]*s1 + w[168+c]*s2 + w[248+c]*s3);
        atomicAdd(dst + 48 + c, v2*INV_NN);
    }
    // i3=6 (ch 64 + c*3 + k), i3=7 (ch 112 + c*3 + k)
    #pragma unroll
    for (int c=0;c<16;c++){
        #pragma unroll
        for (int k=0;k<3;k++){
            float v6 = ALPHA_V6*(w[32+c]*c01[k] + w[48+c]*c10[k] + w[112+c]*c12[k]
                               + w[128+c]*c21[k] + w[192+c]*c23[k] + w[208+c]*c32[k]);
            atomicAdd(dst + 64 + c*3 + k, v6*INV_NN);
            float v7 = (w[96+c]*c11[k] + w[176+c]*c22[k] + w[256+c]*c33[k]);
            atomicAdd(dst + 112 + c*3 + k, v7*INV_NN);
        }
    }
}

// ============================================================================
__global__ void gate_kernel(){
    int n = blockIdx.x*blockDim.x + threadIdx.x;
    if (n >= NN) return;
    const float* x = g_x1 + (size_t)n*160;
    float* o = g_gate + (size_t)n*128;
    #pragma unroll
    for (int c=0;c<16;c++){
        o[c]    = fmaxf(x[c], 0.f);
        o[16+c] = tanhf(x[16+c]);
    }
    float g[32];
    #pragma unroll
    for (int c=0;c<8;c++){
        g[c]    = fmaxf(x[32+c], 0.f);
        g[8+c]  = tanhf(x[40+c]);
        g[16+c] = fmaxf(x[48+c], 0.f);
        g[24+c] = tanhf(x[56+c]);
    }
    #pragma unroll
    for (int c=0;c<32;c++){
        float gv = g[c];
        o[32+c*3+0] = x[64+c*3+0]*gv;
        o[32+c*3+1] = x[64+c*3+1]*gv;
        o[32+c*3+2] = x[64+c*3+2]*gv;
    }
}

// ============================================================================
__global__ void tp2_kernel(const int* __restrict__ esrc, const int* __restrict__ edst){
    __shared__ float cg0;
    __shared__ float cg110[9];
    if (threadIdx.x == 0) cg0 = g_cg[OFF000];
    if (threadIdx.x < 9) cg110[threadIdx.x] = g_cg[OFF110 + threadIdx.x];
    __syncthreads();
    int e = blockIdx.x*blockDim.x + threadIdx.x;
    if (e >= NE) return;
    int s = esrc[e], d = edst[e];
    const float* x = g_gate + (size_t)s*128;
    const float* w = g_w2 + (size_t)e*32;
    float sh1[3];
    sh1[0]=g_sh[(size_t)e*16+1]; sh1[1]=g_sh[(size_t)e*16+2]; sh1[2]=g_sh[(size_t)e*16+3];
    float val = 0.f;
    #pragma unroll
    for (int u=0;u<16;u++) val += x[u]*w[u];
    val *= cg0;
    float v2 = 0.f;
    #pragma unroll
    for (int u=0;u<16;u++){
        const float* av = x + 32 + u*3;
        float t = 0.f;
        #pragma unroll
        for (int i=0;i<3;i++){
            #pragma unroll
            for (int j=0;j<3;j++) t += av[i]*sh1[j]*cg110[i*3+j];
        }
        v2 += w[16+u]*t;
    }
    val = (val + v2)*ALPHA_TP2*INV_NN;
    atomicAdd(g_nodeout + d, val);
}

// ============================================================================
__global__ void final_kernel(const int* __restrict__ batch, float* __restrict__ dout){
    int n = blockIdx.x*blockDim.x + threadIdx.x;
    if (n >= NN) return;
    atomicAdd(dout + batch[n], g_nodeout[n]*INV_SQRT_N);
}

// ============================================================================
extern "C" void kernel_launch(void* const* d_in, const int* in_sizes, int n_in,
                              void* d_out, int out_size){
    const float* pos     = (const float*)d_in[0];
    const float* w_fc1_1 = (const float*)d_in[1];
    const float* w_fc1_2 = (const float*)d_in[2];
    const float* w_fc2_1 = (const float*)d_in[3];
    const float* w_fc2_2 = (const float*)d_in[4];
    const int*   esrc    = (const int*)d_in[5];
    const int*   edst    = (const int*)d_in[6];
    const int*   batch   = (const int*)d_in[7];
    float* dout = (float*)d_out;

    cg_init_kernel<<<1, 672>>>();
    zero_kernel<<<(NN*160 + 255)/256, 256>>>(dout);
    edge_geom_kernel<<<NE/256, 256>>>(pos, esrc, edst);

    fch_kernel<<<NE/32, 256>>>(w_fc1_1);
    sgemm_kernel<272><<<dim3(NE/64, 5), 256>>>(w_fc1_2);
    tp1_kernel<<<NE/256, 256>>>(esrc, edst);
    gate_kernel<<<(NN + 255)/256, 256>>>();

    fch_kernel<<<NE/32, 256>>>(w_fc2_1);
    sgemm_kernel<32><<<dim3(NE/64, 1), 256>>>(w_fc2_2);
    tp2_kernel<<<NE/256, 256>>>(esrc, edst);
    final_kernel<<<(NN + 255)/256, 256>>>(batch, dout);
}

// round 10
// speedup vs baseline: 4.9777x; 4.9777x over previous
#include <cuda_runtime.h>
#include <cuda_bf16.h>
#include <math.h>
#include <stdint.h>

#define NE 640000
#define NN 20000
#define NG 16
#define TBL 8192

// ---- device scratch (no allocations allowed) ----
__device__ float g_sh [(size_t)NE * 16];
__device__ float g_d  [(size_t)NE];
__device__ float g_x0 [(size_t)NN * 16];
__device__ float g_x1 [(size_t)NN * 160];
__device__ float g_gate[(size_t)NN * 128];
__device__ float g_nodeout[NN];
__device__ float g_cg[651];
__device__ float g_tbl1[(size_t)TBL * 272];
__device__ float g_tbl2[(size_t)TBL * 32];

// CG table offsets, layout (i*d2+j)*d3+k
#define OFF000 0
#define OFF110 1
#define OFF220 10
#define OFF330 35
#define OFF011 84
#define OFF101 93
#define OFF111 102
#define OFF121 129
#define OFF211 174
#define OFF221 219
#define OFF231 294
#define OFF321 399
#define OFF331 504
#define CGTOT  651

#define INV_NN     0.17677669529663687f   // 1/sqrt(E/N)=1/sqrt(32)
#define FCH_SCALE  0.02795084971874737f   // sqrt(2/10)/16
#define ALPHA_S    0.5f
#define ALPHA_V6   0.7071067811865476f
#define ALPHA_TP2  0.17677669529663687f   // sqrt(1/32)
#define INV_SQRT_N 0.007071067811865475f  // 1/sqrt(20000)

#define SQ3f   1.7320508075688772f
#define SQ5f   2.23606797749979f
#define SQ7f   2.6457513110645907f
#define SQ15f  3.872983346207417f
#define SQ42f  6.48074069840786f
#define SQ70f  8.366600265340756f
#define SQ105f 10.246950765959598f
#define SQRT10f 3.1622776601683795f

// ---- vectorized global reduction (sm_90+) ----
__device__ __forceinline__ void red4(float* p, float4 v){
    asm volatile("red.global.add.v4.f32 [%0], {%1,%2,%3,%4};"
                 :: "l"(p), "f"(v.x), "f"(v.y), "f"(v.z), "f"(v.w) : "memory");
}

__device__ __forceinline__ float4 lerp4(float4 a, float4 b, float f){
    return make_float4(a.x + f*(b.x-a.x), a.y + f*(b.y-a.y),
                       a.z + f*(b.z-a.z), a.w + f*(b.w-a.w));
}

// ============================================================================
// CG init (mirrors reference exactly, fp64)
// ============================================================================
__device__ double dfact(int n){ double r=1.0; for(int i=2;i<=n;i++) r*= (double)i; return r; }

__device__ double cg_complex_d(int j1,int m1,int j2,int m2,int j3,int m3){
    if (m1+m2 != m3) return 0.0;
    double pref = sqrt((2.0*j3+1.0)*dfact(j3+j1-j2)*dfact(j3-j1+j2)*dfact(j1+j2-j3)/dfact(j1+j2+j3+1));
    pref *= sqrt(dfact(j3+m3)*dfact(j3-m3)*dfact(j1-m1)*dfact(j1+m1)*dfact(j2-m2)*dfact(j2+m2));
    double s = 0.0;
    for (int k=0; k<=j1+j2-j3; k++){
        int e2=j1-m1-k, e3=j2+m2-k, e4=j3-j2+m1+k, e5=j3-j1-m2+k;
        if (e2<0||e3<0||e4<0||e5<0) continue;
        double den = dfact(k)*dfact(j1+j2-j3-k)*dfact(e2)*dfact(e3)*dfact(e4)*dfact(e5);
        s += ((k&1)? -1.0:1.0)/den;
    }
    return pref*s;
}

__device__ void build_U(int l, double* Ur, double* Ui){
    int d = 2*l+1;
    for (int i=0;i<d*d;i++){ Ur[i]=0.0; Ui[i]=0.0; }
    Ur[l*d+l] = 1.0;
    const double is2 = 0.70710678118654752440;
    for (int m=1;m<=l;m++){
        double sgn = (m&1)? -1.0:1.0;
        Ur[(l+m)*d+(l+m)] = sgn*is2;
        Ur[(l+m)*d+(l-m)] = is2;
        Ui[(l-m)*d+(l+m)] = -sgn*is2;
        Ui[(l-m)*d+(l-m)] = is2;
    }
}

__global__ void cg_init_kernel(){
    const int L1[13]  = {0,1,2,3,0,1,1,1,2,2,2,3,3};
    const int L2[13]  = {0,1,2,3,1,0,1,2,1,2,3,2,3};
    const int L3[13]  = {0,0,0,0,1,1,1,1,1,1,1,1,1};
    const int OFF[14] = {0,1,10,35,84,93,102,129,174,219,294,399,504,651};
    __shared__ double sC[CGTOT], sTr[CGTOT], sTi[CGTOT];
    int tid = threadIdx.x;
    int combo = -1, r = 0;
    if (tid < CGTOT){
        for (int t=0;t<13;t++)
            if (tid >= OFF[t] && tid < OFF[t+1]) { combo=t; r=tid-OFF[t]; break; }
    }
    if (combo >= 0){
        int l1=L1[combo], l2=L2[combo], l3=L3[combo];
        int d2=2*l2+1, d3=2*l3+1;
        int c=r%d3, b=(r/d3)%d2, a=r/(d3*d2);
        sC[tid] = cg_complex_d(l1, a-l1, l2, b-l2, l3, c-l3);
    }
    __syncthreads();
    if (combo >= 0){
        int l1=L1[combo], l2=L2[combo], l3=L3[combo];
        int d1=2*l1+1, d2=2*l2+1, d3=2*l3+1;
        int k=r%d3, j=(r/d3)%d2, i=r/(d3*d2);
        double U1r[49],U1i[49],U2r[49],U2i[49],U3r[9],U3i[9];
        build_U(l1,U1r,U1i); build_U(l2,U2r,U2i); build_U(l3,U3r,U3i);
        double tr=0.0, ti=0.0;
        for (int a=0;a<d1;a++){
            double r1=U1r[i*d1+a], i1=U1i[i*d1+a];
            if (r1==0.0 && i1==0.0) continue;
            for (int b=0;b<d2;b++){
                double r2=U2r[j*d2+b], i2=U2i[j*d2+b];
                if (r2==0.0 && i2==0.0) continue;
                double pr=r1*r2-i1*i2, pi=r1*i2+i1*r2;
                for (int c=0;c<d3;c++){
                    double cv = sC[OFF[combo]+(a*d2+b)*d3+c];
                    if (cv==0.0) continue;
                    double r3=U3r[k*d3+c], i3=U3i[k*d3+c];
                    tr += (pr*r3 + pi*i3)*cv;   // * conj(U3)
                    ti += (pi*r3 - pr*i3)*cv;
                }
            }
        }
        sTr[tid]=tr; sTi[tid]=ti;
    }
    __syncthreads();
    if (tid < 13){
        int o0=OFF[tid], o1=OFF[tid+1];
        double sa=0.0, sb=0.0;
        for (int q=o0;q<o1;q++){ sa += fabs(sTr[q]); sb += fabs(sTi[q]); }
        bool useR = (sa >= sb);
        double nrm = 0.0;
        for (int q=o0;q<o1;q++){ double v = useR? sTr[q]:sTi[q]; nrm += v*v; }
        double inv = 1.0/sqrt(nrm);
        for (int q=o0;q<o1;q++){ double v = useR? sTr[q]:sTi[q]; g_cg[q] = (float)(v*inv); }
    }
}

// ============================================================================
__global__ void zero_kernel(float* __restrict__ dout){
    int i = blockIdx.x*blockDim.x + threadIdx.x;
    if (i < NN*16)  g_x0[i] = 0.f;
    if (i < NN*160) g_x1[i] = 0.f;
    if (i < NN)     g_nodeout[i] = 0.f;
    if (i < NG)     dout[i] = 0.f;
}

// ============================================================================
// edge geometry: d, sh; scatter sh into x0[dst]
// ============================================================================
__global__ void edge_geom_kernel(const float* __restrict__ pos,
                                 const int* __restrict__ esrc,
                                 const int* __restrict__ edst){
    int e = blockIdx.x*blockDim.x + threadIdx.x;
    if (e >= NE) return;
    int s = esrc[e], d = edst[e];
    float ex = pos[d*3+0]-pos[s*3+0];
    float ey = pos[d*3+1]-pos[s*3+1];
    float ez = pos[d*3+2]-pos[s*3+2];
    float dn = sqrtf(ex*ex+ey*ey+ez*ez + 1e-12f);
    float inv = 1.f/dn;
    float x = ex*inv, y = ey*inv, z = ez*inv;
    float xx=x*x, yy=y*y, zz=z*z;
    float sh[16];
    sh[0]=1.f;
    sh[1]=SQ3f*y; sh[2]=SQ3f*z; sh[3]=SQ3f*x;
    sh[4]=SQ15f*x*y; sh[5]=SQ15f*y*z; sh[6]=0.5f*SQ5f*(3.f*zz-1.f);
    sh[7]=SQ15f*x*z; sh[8]=0.5f*SQ15f*(xx-yy);
    sh[9] =0.25f*SQ70f*y*(3.f*xx-yy);
    sh[10]=SQ105f*x*y*z;
    sh[11]=0.25f*SQ42f*y*(5.f*zz-1.f);
    sh[12]=0.5f*SQ7f*z*(5.f*zz-3.f);
    sh[13]=0.25f*SQ42f*x*(5.f*zz-1.f);
    sh[14]=0.5f*SQ105f*z*(xx-yy);
    sh[15]=0.25f*SQ70f*x*(xx-3.f*yy);

    float4* shp = reinterpret_cast<float4*>(g_sh + (size_t)e*16);
    shp[0]=make_float4(sh[0],sh[1],sh[2],sh[3]);
    shp[1]=make_float4(sh[4],sh[5],sh[6],sh[7]);
    shp[2]=make_float4(sh[8],sh[9],sh[10],sh[11]);
    shp[3]=make_float4(sh[12],sh[13],sh[14],sh[15]);

    g_d[e] = dn;

    float* x0 = g_x0 + (size_t)d*16;
    red4(x0+0,  make_float4(sh[0]*INV_NN, sh[1]*INV_NN, sh[2]*INV_NN, sh[3]*INV_NN));
    red4(x0+4,  make_float4(sh[4]*INV_NN, sh[5]*INV_NN, sh[6]*INV_NN, sh[7]*INV_NN));
    red4(x0+8,  make_float4(sh[8]*INV_NN, sh[9]*INV_NN, sh[10]*INV_NN, sh[11]*INV_NN));
    red4(x0+12, make_float4(sh[12]*INV_NN, sh[13]*INV_NN, sh[14]*INV_NN, sh[15]*INV_NN));
}

// ============================================================================
// table build: w(d) on TBL-point grid over [0, 3.2].
// Output table selected INSIDE the kernel (device symbol; host code must not
// take its address).
// ============================================================================
template<int NOUT>
__global__ void table_kernel(const float* __restrict__ Wa,
                             const float* __restrict__ Wb){
    float* tbl = (NOUT == 272) ? g_tbl1 : g_tbl2;
    __shared__ float semb[32][10];
    __shared__ float hh[256][33];
    int r0 = blockIdx.x*32;
    int t = threadIdx.x;
    const float stepw = 3.2f/11.f;
    const float dgrid = 3.2f/(float)(TBL-1);
    for (int i=t; i<320; i+=256){
        int rr = i/10, k = i%10;
        float dv = (float)(r0+rr)*dgrid;
        float c = (float)(k+1)*stepw;
        float u = (dv-c)/stepw;
        float u2 = u*u;
        float f = 0.f;
        if (u2 < 1.f){
            float den = fmaxf(1.f-u2, 1e-6f);
            f = 1.14136f*expf(-u2/den)*SQRT10f;
        }
        semb[rr][k] = f;
    }
    __syncthreads();
    {
        float w[10];
        #pragma unroll
        for (int k=0;k<10;k++) w[k] = Wa[k*256 + t];
        #pragma unroll 4
        for (int rr=0; rr<32; rr++){
            float acc = 0.f;
            #pragma unroll
            for (int k=0;k<10;k++) acc += semb[rr][k]*w[k];
            hh[t][rr] = fmaxf(acc, 0.f)*FCH_SCALE;
        }
    }
    __syncthreads();
    for (int k=t; k<NOUT; k+=256){
        float acc[32];
        #pragma unroll
        for (int r=0;r<32;r++) acc[r] = 0.f;
        for (int j=0;j<256;j++){
            float wv = Wb[j*NOUT + k];
            #pragma unroll
            for (int r=0;r<32;r++) acc[r] += hh[j][r]*wv;
        }
        for (int r=0;r<32;r++) tbl[(size_t)(r0+r)*NOUT + k] = acc[r];
    }
}

// ============================================================================
// TP1: per edge, weights lerped from table, scatter into g_x1[dst]
// ============================================================================
template<int D1,int D2>
__device__ __forceinline__ void contr3(const float* a, const float* b,
                                       const float* cgt, float* o){
    o[0]=0.f; o[1]=0.f; o[2]=0.f;
    #pragma unroll
    for (int i=0;i<D1;i++){
        #pragma unroll
        for (int j=0;j<D2;j++){
            float p = a[i]*b[j];
            const float* c = cgt + (i*D2+j)*3;
            o[0] += p*c[0]; o[1] += p*c[1]; o[2] += p*c[2];
        }
    }
}

__global__ void tp1_kernel(const int* __restrict__ esrc, const int* __restrict__ edst){
    __shared__ float cg[CGTOT];
    for (int i=threadIdx.x; i<CGTOT; i+=blockDim.x) cg[i] = g_cg[i];
    __syncthreads();
    int e = blockIdx.x*blockDim.x + threadIdx.x;
    if (e >= NE) return;
    float dn = g_d[e];
    if (dn >= 3.2f) return;          // all radial bases vanish -> w == 0
    int s = esrc[e], d = edst[e];

    float xf = dn * ((float)(TBL-1)/3.2f);
    int i0 = (int)xf; if (i0 > TBL-2) i0 = TBL-2;
    float fr = xf - (float)i0;
    const float4* T0 = reinterpret_cast<const float4*>(g_tbl1 + (size_t)i0*272);
    const float4* T1 = reinterpret_cast<const float4*>(g_tbl1 + (size_t)(i0+1)*272);
    #define WL1(slot) lerp4(T0[(slot)], T1[(slot)], fr)

    float a[16], b[16];
    const float4* xp = reinterpret_cast<const float4*>(g_x0 + (size_t)s*16);
    #pragma unroll
    for (int i=0;i<4;i++){ float4 v = xp[i]; a[i*4]=v.x; a[i*4+1]=v.y; a[i*4+2]=v.z; a[i*4+3]=v.w; }
    const float4* shp = reinterpret_cast<const float4*>(g_sh + (size_t)e*16);
    #pragma unroll
    for (int i=0;i<4;i++){ float4 v = shp[i]; b[i*4]=v.x; b[i*4+1]=v.y; b[i*4+2]=v.z; b[i*4+3]=v.w; }

    // scalar contractions (l,l,0)
    float s0 = a[0]*b[0]*cg[OFF000];
    float s1 = 0.f;
    #pragma unroll
    for (int i=0;i<3;i++){ float ai=a[1+i];
        #pragma unroll
        for (int j=0;j<3;j++) s1 += ai*b[1+j]*cg[OFF110+i*3+j]; }
    float s2 = 0.f;
    #pragma unroll
    for (int i=0;i<5;i++){ float ai=a[4+i];
        #pragma unroll
        for (int j=0;j<5;j++) s2 += ai*b[4+j]*cg[OFF220+i*5+j]; }
    float s3 = 0.f;
    #pragma unroll
    for (int i=0;i<7;i++){ float ai=a[9+i];
        #pragma unroll
        for (int j=0;j<7;j++) s3 += ai*b[9+j]*cg[OFF330+i*7+j]; }

    // vector contractions (l1,l2,1)
    float c01[3],c10[3],c12[3],c21[3],c23[3],c32[3],c11[3],c22[3],c33[3];
    contr3<1,3>(a+0, b+1, cg+OFF011, c01);
    contr3<3,1>(a+1, b+0, cg+OFF101, c10);
    contr3<3,5>(a+1, b+4, cg+OFF121, c12);
    contr3<5,3>(a+4, b+1, cg+OFF211, c21);
    contr3<5,7>(a+4, b+9, cg+OFF231, c23);
    contr3<7,5>(a+9, b+4, cg+OFF321, c32);
    contr3<3,3>(a+1, b+1, cg+OFF111, c11);
    contr3<5,5>(a+4, b+4, cg+OFF221, c22);
    contr3<7,7>(a+9, b+9, cg+OFF331, c33);

    float* dst = g_x1 + (size_t)d*160;
    const float AS = ALPHA_S*INV_NN;

    // i3=0: out ch 0..15 ; weights w[c], w[64+c], w[144+c], w[224+c]
    #pragma unroll
    for (int q=0;q<4;q++){
        float4 w0=WL1(0+q), w1=WL1(16+q), w2=WL1(36+q), w3=WL1(56+q);
        float4 v;
        v.x = AS*(w0.x*s0 + w1.x*s1 + w2.x*s2 + w3.x*s3);
        v.y = AS*(w0.y*s0 + w1.y*s1 + w2.y*s2 + w3.y*s3);
        v.z = AS*(w0.z*s0 + w1.z*s1 + w2.z*s2 + w3.z*s3);
        v.w = AS*(w0.w*s0 + w1.w*s1 + w2.w*s2 + w3.w*s3);
        red4(dst + q*4, v);
    }
    // i3=2: out ch 32..39 ; weights w[16+c], w[80+c], w[160+c], w[240+c]
    #pragma unroll
    for (int q=0;q<2;q++){
        float4 w0=WL1(4+q), w1=WL1(20+q), w2=WL1(40+q), w3=WL1(60+q);
        float4 v;
        v.x = AS*(w0.x*s0 + w1.x*s1 + w2.x*s2 + w3.x*s3);
        v.y = AS*(w0.y*s0 + w1.y*s1 + w2.y*s2 + w3.y*s3);
        v.z = AS*(w0.z*s0 + w1.z*s1 + w2.z*s2 + w3.z*s3);
        v.w = AS*(w0.w*s0 + w1.w*s1 + w2.w*s2 + w3.w*s3);
        red4(dst + 32 + q*4, v);
    }
    // i3=4: out ch 48..55 ; weights w[24+c], w[88+c], w[168+c], w[248+c]
    #pragma unroll
    for (int q=0;q<2;q++){
        float4 w0=WL1(6+q), w1=WL1(22+q), w2=WL1(42+q), w3=WL1(62+q);
        float4 v;
        v.x = AS*(w0.x*s0 + w1.x*s1 + w2.x*s2 + w3.x*s3);
        v.y = AS*(w0.y*s0 + w1.y*s1 + w2.y*s2 + w3.y*s3);
        v.z = AS*(w0.z*s0 + w1.z*s1 + w2.z*s2 + w3.z*s3);
        v.w = AS*(w0.w*s0 + w1.w*s1 + w2.w*s2 + w3.w*s3);
        red4(dst + 48 + q*4, v);
    }
    // i3=6: out ch 64 + c*3 + k ; weights w[32+c],w[48+c],w[112+c],w[128+c],w[192+c],w[208+c]
    const float A6 = ALPHA_V6*INV_NN;
    #pragma unroll
    for (int q=0;q<4;q++){
        float4 wa=WL1(8+q), wb=WL1(12+q), wc=WL1(28+q), wd=WL1(32+q), we=WL1(48+q), wf=WL1(52+q);
        float fa[4]={wa.x,wa.y,wa.z,wa.w}, fb[4]={wb.x,wb.y,wb.z,wb.w};
        float fc[4]={wc.x,wc.y,wc.z,wc.w}, fd[4]={wd.x,wd.y,wd.z,wd.w};
        float fe[4]={we.x,we.y,we.z,we.w}, ff[4]={wf.x,wf.y,wf.z,wf.w};
        float o[12];
        #pragma unroll
        for (int cc=0;cc<4;cc++){
            #pragma unroll
            for (int k=0;k<3;k++)
                o[cc*3+k] = A6*(fa[cc]*c01[k] + fb[cc]*c10[k] + fc[cc]*c12[k]
                              + fd[cc]*c21[k] + fe[cc]*c23[k] + ff[cc]*c32[k]);
        }
        red4(dst + 64 + q*12 + 0, make_float4(o[0],o[1],o[2],o[3]));
        red4(dst + 64 + q*12 + 4, make_float4(o[4],o[5],o[6],o[7]));
        red4(dst + 64 + q*12 + 8, make_float4(o[8],o[9],o[10],o[11]));
    }
    // i3=7: out ch 112 + c*3 + k ; weights w[96+c], w[176+c], w[256+c] (alpha=1)
    #pragma unroll
    for (int q=0;q<4;q++){
        float4 wg=WL1(24+q), wh=WL1(44+q), wi=WL1(64+q);
        float fg[4]={wg.x,wg.y,wg.z,wg.w}, fh[4]={wh.x,wh.y,wh.z,wh.w}, fi[4]={wi.x,wi.y,wi.z,wi.w};
        float o[12];
        #pragma unroll
        for (int cc=0;cc<4;cc++){
            #pragma unroll
            for (int k=0;k<3;k++)
                o[cc*3+k] = INV_NN*(fg[cc]*c11[k] + fh[cc]*c22[k] + fi[cc]*c33[k]);
        }
        red4(dst + 112 + q*12 + 0, make_float4(o[0],o[1],o[2],o[3]));
        red4(dst + 112 + q*12 + 4, make_float4(o[4],o[5],o[6],o[7]));
        red4(dst + 112 + q*12 + 8, make_float4(o[8],o[9],o[10],o[11]));
    }
    #undef WL1
}

// ============================================================================
__global__ void gate_kernel(){
    int n = blockIdx.x*blockDim.x + threadIdx.x;
    if (n >= NN) return;
    const float* x = g_x1 + (size_t)n*160;
    float* o = g_gate + (size_t)n*128;
    #pragma unroll
    for (int c=0;c<16;c++){
        o[c]    = fmaxf(x[c], 0.f);
        o[16+c] = tanhf(x[16+c]);
    }
    float g[32];
    #pragma unroll
    for (int c=0;c<8;c++){
        g[c]    = fmaxf(x[32+c], 0.f);
        g[8+c]  = tanhf(x[40+c]);
        g[16+c] = fmaxf(x[48+c], 0.f);
        g[24+c] = tanhf(x[56+c]);
    }
    #pragma unroll
    for (int c=0;c<32;c++){
        float gv = g[c];
        o[32+c*3+0] = x[64+c*3+0]*gv;
        o[32+c*3+1] = x[64+c*3+1]*gv;
        o[32+c*3+2] = x[64+c*3+2]*gv;
    }
}

// ============================================================================
__global__ void tp2_kernel(const int* __restrict__ esrc, const int* __restrict__ edst){
    __shared__ float cg0;
    __shared__ float cg110[9];
    if (threadIdx.x == 0) cg0 = g_cg[OFF000];
    if (threadIdx.x < 9) cg110[threadIdx.x] = g_cg[OFF110 + threadIdx.x];
    __syncthreads();
    int e = blockIdx.x*blockDim.x + threadIdx.x;
    if (e >= NE) return;
    float dn = g_d[e];
    if (dn >= 3.2f) return;          // w2 == 0
    int s = esrc[e], d = edst[e];

    float xf = dn * ((float)(TBL-1)/3.2f);
    int i0 = (int)xf; if (i0 > TBL-2) i0 = TBL-2;
    float fr = xf - (float)i0;
    const float4* T0 = reinterpret_cast<const float4*>(g_tbl2 + (size_t)i0*32);
    const float4* T1 = reinterpret_cast<const float4*>(g_tbl2 + (size_t)(i0+1)*32);
    float w[32];
    #pragma unroll
    for (int q=0;q<8;q++){
        float4 v = lerp4(T0[q], T1[q], fr);
        w[q*4]=v.x; w[q*4+1]=v.y; w[q*4+2]=v.z; w[q*4+3]=v.w;
    }

    const float* x = g_gate + (size_t)s*128;
    float sh1[3];
    sh1[0]=g_sh[(size_t)e*16+1]; sh1[1]=g_sh[(size_t)e*16+2]; sh1[2]=g_sh[(size_t)e*16+3];
    float val = 0.f;
    #pragma unroll
    for (int u=0;u<16;u++) val += x[u]*w[u];
    val *= cg0;
    float v2 = 0.f;
    #pragma unroll
    for (int u=0;u<16;u++){
        const float* av = x + 32 + u*3;
        float t = 0.f;
        #pragma unroll
        for (int i=0;i<3;i++){
            #pragma unroll
            for (int j=0;j<3;j++) t += av[i]*sh1[j]*cg110[i*3+j];
        }
        v2 += w[16+u]*t;
    }
    val = (val + v2)*ALPHA_TP2*INV_NN;
    atomicAdd(g_nodeout + d, val);
}

// ============================================================================
__global__ void final_kernel(const int* __restrict__ batch, float* __restrict__ dout){
    int n = blockIdx.x*blockDim.x + threadIdx.x;
    if (n >= NN) return;
    atomicAdd(dout + batch[n], g_nodeout[n]*INV_SQRT_N);
}

// ============================================================================
extern "C" void kernel_launch(void* const* d_in, const int* in_sizes, int n_in,
                              void* d_out, int out_size){
    const float* pos     = (const float*)d_in[0];
    const float* w_fc1_1 = (const float*)d_in[1];
    const float* w_fc1_2 = (const float*)d_in[2];
    const float* w_fc2_1 = (const float*)d_in[3];
    const float* w_fc2_2 = (const float*)d_in[4];
    const int*   esrc    = (const int*)d_in[5];
    const int*   edst    = (const int*)d_in[6];
    const int*   batch   = (const int*)d_in[7];
    float* dout = (float*)d_out;

    cg_init_kernel<<<1, 672>>>();
    zero_kernel<<<(NN*160 + 255)/256, 256>>>(dout);
    edge_geom_kernel<<<NE/256, 256>>>(pos, esrc, edst);

    table_kernel<272><<<TBL/32, 256>>>(w_fc1_1, w_fc1_2);
    table_kernel<32> <<<TBL/32, 256>>>(w_fc2_1, w_fc2_2);

    tp1_kernel<<<NE/256, 256>>>(esrc, edst);
    gate_kernel<<<(NN + 255)/256, 256>>>();
    tp2_kernel<<<NE/256, 256>>>(esrc, edst);
    final_kernel<<<(NN + 255)/256, 256>>>(batch, dout);
}

// round 13
// speedup vs baseline: 7.4349x; 1.4937x over previous
#include <cuda_runtime.h>
#include <cuda_bf16.h>
#include <math.h>
#include <stdint.h>

#define NE 640000
#define NN 20000
#define NG 16
#define TBL 4096

// ---- device scratch (no allocations allowed) ----
__device__ float g_sh [(size_t)NE * 16];
__device__ float g_d  [(size_t)NE];
__device__ float g_x0 [(size_t)NN * 16];
__device__ float g_x1 [(size_t)NN * 160];
__device__ float g_gate[(size_t)NN * 128];
__device__ float g_nodeout[NN];
__device__ float g_cg[651];
__device__ float g_tbl1[(size_t)TBL * 272];
__device__ float g_tbl2[(size_t)TBL * 32];

// CG table offsets, layout (i*d2+j)*d3+k
#define OFF000 0
#define OFF110 1
#define OFF220 10
#define OFF330 35
#define OFF011 84
#define OFF101 93
#define OFF111 102
#define OFF121 129
#define OFF211 174
#define OFF221 219
#define OFF231 294
#define OFF321 399
#define OFF331 504
#define CGTOT  651

#define INV_NN     0.17677669529663687f   // 1/sqrt(E/N)=1/sqrt(32)
#define FCH_SCALE  0.02795084971874737f   // sqrt(2/10)/16
#define ALPHA_S    0.5f
#define ALPHA_V6   0.7071067811865476f
#define ALPHA_TP2  0.17677669529663687f   // sqrt(1/32)
#define INV_SQRT_N 0.007071067811865475f  // 1/sqrt(20000)

#define SQ3f   1.7320508075688772f
#define SQ5f   2.23606797749979f
#define SQ7f   2.6457513110645907f
#define SQ15f  3.872983346207417f
#define SQ42f  6.48074069840786f
#define SQ70f  8.366600265340756f
#define SQ105f 10.246950765959598f
#define SQRT10f 3.1622776601683795f

// ---- vectorized global reduction (sm_90+) ----
__device__ __forceinline__ void red4(float* p, float4 v){
    asm volatile("red.global.add.v4.f32 [%0], {%1,%2,%3,%4};"
                 :: "l"(p), "f"(v.x), "f"(v.y), "f"(v.z), "f"(v.w) : "memory");
}

__device__ __forceinline__ float4 lerp4(float4 a, float4 b, float f){
    return make_float4(a.x + f*(b.x-a.x), a.y + f*(b.y-a.y),
                       a.z + f*(b.z-a.z), a.w + f*(b.w-a.w));
}

// ============================================================================
// CG init (mirrors reference exactly, fp64). One block per CG tensor;
// U matrices + scratch live in SHARED memory. Max tensor size = 7*7*3 = 147.
// ============================================================================
#define CGMAX 147

__device__ double dfact(int n){ double r=1.0; for(int i=2;i<=n;i++) r*= (double)i; return r; }

__device__ double cg_complex_d(int j1,int m1,int j2,int m2,int j3,int m3){
    if (m1+m2 != m3) return 0.0;
    double pref = sqrt((2.0*j3+1.0)*dfact(j3+j1-j2)*dfact(j3-j1+j2)*dfact(j1+j2-j3)/dfact(j1+j2+j3+1));
    pref *= sqrt(dfact(j3+m3)*dfact(j3-m3)*dfact(j1-m1)*dfact(j1+m1)*dfact(j2-m2)*dfact(j2+m2));
    double s = 0.0;
    for (int k=0; k<=j1+j2-j3; k++){
        int e2=j1-m1-k, e3=j2+m2-k, e4=j3-j2+m1+k, e5=j3-j1-m2+k;
        if (e2<0||e3<0||e4<0||e5<0) continue;
        double den = dfact(k)*dfact(j1+j2-j3-k)*dfact(e2)*dfact(e3)*dfact(e4)*dfact(e5);
        s += ((k&1)? -1.0:1.0)/den;
    }
    return pref*s;
}

__device__ void build_U(int l, double* Ur, double* Ui){
    int d = 2*l+1;
    for (int i=0;i<d*d;i++){ Ur[i]=0.0; Ui[i]=0.0; }
    Ur[l*d+l] = 1.0;
    const double is2 = 0.70710678118654752440;
    for (int m=1;m<=l;m++){
        double sgn = (m&1)? -1.0:1.0;
        Ur[(l+m)*d+(l+m)] = sgn*is2;
        Ur[(l+m)*d+(l-m)] = is2;
        Ui[(l-m)*d+(l+m)] = -sgn*is2;
        Ui[(l-m)*d+(l-m)] = is2;
    }
}

__global__ void cg_init_kernel(){
    const int L1[13]  = {0,1,2,3,0,1,1,1,2,2,2,3,3};
    const int L2[13]  = {0,1,2,3,1,0,1,2,1,2,3,2,3};
    const int L3[13]  = {0,0,0,0,1,1,1,1,1,1,1,1,1};
    const int OFF[14] = {0,1,10,35,84,93,102,129,174,219,294,399,504,651};
    int combo = blockIdx.x;           // 0..12
    int l1=L1[combo], l2=L2[combo], l3=L3[combo];
    int d1=2*l1+1, d2=2*l2+1, d3=2*l3+1;
    int base = OFF[combo];
    int cnt = OFF[combo+1] - base;    // <= 147 (7*7*3)

    __shared__ double U1r[49],U1i[49],U2r[49],U2i[49],U3r[9],U3i[9];
    __shared__ double sC[CGMAX], sTr[CGMAX], sTi[CGMAX];
    int t = threadIdx.x;
    if (t == 0) build_U(l1, U1r, U1i);
    if (t == 1) build_U(l2, U2r, U2i);
    if (t == 2) build_U(l3, U3r, U3i);

    // phase 0: complex CG values (real)
    for (int r = t; r < cnt; r += blockDim.x){
        int c = r % d3, b = (r/d3) % d2, a = r/(d3*d2);
        sC[r] = cg_complex_d(l1, a-l1, l2, b-l2, l3, c-l3);
    }
    __syncthreads();

    // phase 1: T[i,j,k] = sum U1[i,a] U2[j,b] conj(U3[k,c]) C[a,b,c]
    for (int r = t; r < cnt; r += blockDim.x){
        int k = r % d3, j = (r/d3) % d2, i = r/(d3*d2);
        double tr = 0.0, ti = 0.0;
        for (int a=0; a<d1; a++){
            double r1=U1r[i*d1+a], i1=U1i[i*d1+a];
            if (r1==0.0 && i1==0.0) continue;
            for (int b=0; b<d2; b++){
                double r2=U2r[j*d2+b], i2=U2i[j*d2+b];
                if (r2==0.0 && i2==0.0) continue;
                double pr=r1*r2-i1*i2, pi=r1*i2+i1*r2;
                for (int c=0; c<d3; c++){
                    double cv = sC[(a*d2+b)*d3+c];
                    if (cv==0.0) continue;
                    double r3=U3r[k*d3+c], i3=U3i[k*d3+c];
                    tr += (pr*r3 + pi*i3)*cv;   // * conj(U3)
                    ti += (pi*r3 - pr*i3)*cv;
                }
            }
        }
        sTr[r]=tr; sTi[r]=ti;
    }
    __syncthreads();

    // phase 2: choose real/imag by abs-sum, Frobenius-normalize, emit fp32
    if (t == 0){
        double sa=0.0, sb=0.0;
        for (int q=0;q<cnt;q++){ sa += fabs(sTr[q]); sb += fabs(sTi[q]); }
        bool useR = (sa >= sb);
        double nrm = 0.0;
        for (int q=0;q<cnt;q++){ double v = useR? sTr[q]:sTi[q]; nrm += v*v; }
        double inv = 1.0/sqrt(nrm);
        for (int q=0;q<cnt;q++){ double v = useR? sTr[q]:sTi[q]; g_cg[base+q] = (float)(v*inv); }
    }
}

// ============================================================================
__global__ void zero_kernel(float* __restrict__ dout){
    int i = blockIdx.x*blockDim.x + threadIdx.x;
    if (i < NN*16)  g_x0[i] = 0.f;
    if (i < NN*160) g_x1[i] = 0.f;
    if (i < NN)     g_nodeout[i] = 0.f;
    if (i < NG)     dout[i] = 0.f;
}

// ============================================================================
// edge geometry: d, sh; scatter sh into x0[dst]
// ============================================================================
__global__ void edge_geom_kernel(const float* __restrict__ pos,
                                 const int* __restrict__ esrc,
                                 const int* __restrict__ edst){
    int e = blockIdx.x*blockDim.x + threadIdx.x;
    if (e >= NE) return;
    int s = esrc[e], d = edst[e];
    float ex = pos[d*3+0]-pos[s*3+0];
    float ey = pos[d*3+1]-pos[s*3+1];
    float ez = pos[d*3+2]-pos[s*3+2];
    float dn = sqrtf(ex*ex+ey*ey+ez*ez + 1e-12f);
    float inv = 1.f/dn;
    float x = ex*inv, y = ey*inv, z = ez*inv;
    float xx=x*x, yy=y*y, zz=z*z;
    float sh[16];
    sh[0]=1.f;
    sh[1]=SQ3f*y; sh[2]=SQ3f*z; sh[3]=SQ3f*x;
    sh[4]=SQ15f*x*y; sh[5]=SQ15f*y*z; sh[6]=0.5f*SQ5f*(3.f*zz-1.f);
    sh[7]=SQ15f*x*z; sh[8]=0.5f*SQ15f*(xx-yy);
    sh[9] =0.25f*SQ70f*y*(3.f*xx-yy);
    sh[10]=SQ105f*x*y*z;
    sh[11]=0.25f*SQ42f*y*(5.f*zz-1.f);
    sh[12]=0.5f*SQ7f*z*(5.f*zz-3.f);
    sh[13]=0.25f*SQ42f*x*(5.f*zz-1.f);
    sh[14]=0.5f*SQ105f*z*(xx-yy);
    sh[15]=0.25f*SQ70f*x*(xx-3.f*yy);

    float4* shp = reinterpret_cast<float4*>(g_sh + (size_t)e*16);
    shp[0]=make_float4(sh[0],sh[1],sh[2],sh[3]);
    shp[1]=make_float4(sh[4],sh[5],sh[6],sh[7]);
    shp[2]=make_float4(sh[8],sh[9],sh[10],sh[11]);
    shp[3]=make_float4(sh[12],sh[13],sh[14],sh[15]);

    g_d[e] = dn;

    float* x0 = g_x0 + (size_t)d*16;
    red4(x0+0,  make_float4(sh[0]*INV_NN, sh[1]*INV_NN, sh[2]*INV_NN, sh[3]*INV_NN));
    red4(x0+4,  make_float4(sh[4]*INV_NN, sh[5]*INV_NN, sh[6]*INV_NN, sh[7]*INV_NN));
    red4(x0+8,  make_float4(sh[8]*INV_NN, sh[9]*INV_NN, sh[10]*INV_NN, sh[11]*INV_NN));
    red4(x0+12, make_float4(sh[12]*INV_NN, sh[13]*INV_NN, sh[14]*INV_NN, sh[15]*INV_NN));
}

// ============================================================================
// table build: w(d) on TBL-point grid over [0, 3.2].
// 8 grid rows per block (smem 8.3KB -> high occupancy, TBL/8 blocks).
// ============================================================================
template<int NOUT>
__global__ void table_kernel(const float* __restrict__ Wa,
                             const float* __restrict__ Wb){
    float* tbl = (NOUT == 272) ? g_tbl1 : g_tbl2;
    __shared__ float semb[8][10];
    __shared__ float hh[8][256];      // [row][hidden j]
    int r0 = blockIdx.x*8;
    int t = threadIdx.x;
    const float stepw = 3.2f/11.f;
    const float dgrid = 3.2f/(float)(TBL-1);
    if (t < 80){
        int rr = t/10, k = t%10;
        float dv = (float)(r0+rr)*dgrid;
        float c = (float)(k+1)*stepw;
        float u = (dv-c)/stepw;
        float u2 = u*u;
        float f = 0.f;
        if (u2 < 1.f){
            float den = fmaxf(1.f-u2, 1e-6f);
            f = 1.14136f*expf(-u2/den)*SQRT10f;
        }
        semb[rr][k] = f;
    }
    __syncthreads();
    {
        float w[10];
        #pragma unroll
        for (int k=0;k<10;k++) w[k] = Wa[k*256 + t];
        #pragma unroll
        for (int rr=0; rr<8; rr++){
            float acc = 0.f;
            #pragma unroll
            for (int k=0;k<10;k++) acc += semb[rr][k]*w[k];
            hh[rr][t] = fmaxf(acc, 0.f)*FCH_SCALE;
        }
    }
    __syncthreads();
    if (NOUT == 272){
        for (int k=t; k<NOUT; k+=256){
            float acc[8];
            #pragma unroll
            for (int r=0;r<8;r++) acc[r] = 0.f;
            for (int j=0;j<256;j++){
                float wv = Wb[j*NOUT + k];
                #pragma unroll
                for (int r=0;r<8;r++) acc[r] += hh[r][j]*wv;
            }
            #pragma unroll
            for (int r=0;r<8;r++) tbl[(size_t)(r0+r)*NOUT + k] = acc[r];
        }
    } else {
        int k  = t & 31;
        int rr = t >> 5;          // 0..7
        float acc = 0.f;
        for (int j=0;j<256;j++) acc += hh[rr][j]*Wb[j*NOUT + k];
        tbl[(size_t)(r0+rr)*NOUT + k] = acc;
    }
}

// ============================================================================
// TP1: per edge, weights lerped from table, scatter into g_x1[dst]
// ============================================================================
template<int D1,int D2>
__device__ __forceinline__ void contr3(const float* a, const float* b,
                                       const float* cgt, float* o){
    o[0]=0.f; o[1]=0.f; o[2]=0.f;
    #pragma unroll
    for (int i=0;i<D1;i++){
        #pragma unroll
        for (int j=0;j<D2;j++){
            float p = a[i]*b[j];
            const float* c = cgt + (i*D2+j)*3;
            o[0] += p*c[0]; o[1] += p*c[1]; o[2] += p*c[2];
        }
    }
}

__global__ void tp1_kernel(const int* __restrict__ esrc, const int* __restrict__ edst){
    __shared__ float cg[CGTOT];
    for (int i=threadIdx.x; i<CGTOT; i+=blockDim.x) cg[i] = g_cg[i];
    __syncthreads();
    int e = blockIdx.x*blockDim.x + threadIdx.x;
    if (e >= NE) return;
    float dn = g_d[e];
    if (dn >= 3.2f) return;          // all radial bases vanish -> w == 0
    int s = esrc[e], d = edst[e];

    float xf = dn * ((float)(TBL-1)/3.2f);
    int i0 = (int)xf; if (i0 > TBL-2) i0 = TBL-2;
    float fr = xf - (float)i0;
    const float4* T0 = reinterpret_cast<const float4*>(g_tbl1 + (size_t)i0*272);
    const float4* T1 = reinterpret_cast<const float4*>(g_tbl1 + (size_t)(i0+1)*272);
    #define WL1(slot) lerp4(T0[(slot)], T1[(slot)], fr)

    float a[16], b[16];
    const float4* xp = reinterpret_cast<const float4*>(g_x0 + (size_t)s*16);
    #pragma unroll
    for (int i=0;i<4;i++){ float4 v = xp[i]; a[i*4]=v.x; a[i*4+1]=v.y; a[i*4+2]=v.z; a[i*4+3]=v.w; }
    const float4* shp = reinterpret_cast<const float4*>(g_sh + (size_t)e*16);
    #pragma unroll
    for (int i=0;i<4;i++){ float4 v = shp[i]; b[i*4]=v.x; b[i*4+1]=v.y; b[i*4+2]=v.z; b[i*4+3]=v.w; }

    // scalar contractions (l,l,0)
    float s0 = a[0]*b[0]*cg[OFF000];
    float s1 = 0.f;
    #pragma unroll
    for (int i=0;i<3;i++){ float ai=a[1+i];
        #pragma unroll
        for (int j=0;j<3;j++) s1 += ai*b[1+j]*cg[OFF110+i*3+j]; }
    float s2 = 0.f;
    #pragma unroll
    for (int i=0;i<5;i++){ float ai=a[4+i];
        #pragma unroll
        for (int j=0;j<5;j++) s2 += ai*b[4+j]*cg[OFF220+i*5+j]; }
    float s3 = 0.f;
    #pragma unroll
    for (int i=0;i<7;i++){ float ai=a[9+i];
        #pragma unroll
        for (int j=0;j<7;j++) s3 += ai*b[9+j]*cg[OFF330+i*7+j]; }

    // vector contractions (l1,l2,1)
    float c01[3],c10[3],c12[3],c21[3],c23[3],c32[3],c11[3],c22[3],c33[3];
    contr3<1,3>(a+0, b+1, cg+OFF011, c01);
    contr3<3,1>(a+1, b+0, cg+OFF101, c10);
    contr3<3,5>(a+1, b+4, cg+OFF121, c12);
    contr3<5,3>(a+4, b+1, cg+OFF211, c21);
    contr3<5,7>(a+4, b+9, cg+OFF231, c23);
    contr3<7,5>(a+9, b+4, cg+OFF321, c32);
    contr3<3,3>(a+1, b+1, cg+OFF111, c11);
    contr3<5,5>(a+4, b+4, cg+OFF221, c22);
    contr3<7,7>(a+9, b+9, cg+OFF331, c33);

    float* dst = g_x1 + (size_t)d*160;
    const float AS = ALPHA_S*INV_NN;

    // i3=0: out ch 0..15 ; weights w[c], w[64+c], w[144+c], w[224+c]
    #pragma unroll
    for (int q=0;q<4;q++){
        float4 w0=WL1(0+q), w1=WL1(16+q), w2=WL1(36+q), w3=WL1(56+q);
        float4 v;
        v.x = AS*(w0.x*s0 + w1.x*s1 + w2.x*s2 + w3.x*s3);
        v.y = AS*(w0.y*s0 + w1.y*s1 + w2.y*s2 + w3.y*s3);
        v.z = AS*(w0.z*s0 + w1.z*s1 + w2.z*s2 + w3.z*s3);
        v.w = AS*(w0.w*s0 + w1.w*s1 + w2.w*s2 + w3.w*s3);
        red4(dst + q*4, v);
    }
    // i3=2: out ch 32..39 ; weights w[16+c], w[80+c], w[160+c], w[240+c]
    #pragma unroll
    for (int q=0;q<2;q++){
        float4 w0=WL1(4+q), w1=WL1(20+q), w2=WL1(40+q), w3=WL1(60+q);
        float4 v;
        v.x = AS*(w0.x*s0 + w1.x*s1 + w2.x*s2 + w3.x*s3);
        v.y = AS*(w0.y*s0 + w1.y*s1 + w2.y*s2 + w3.y*s3);
        v.z = AS*(w0.z*s0 + w1.z*s1 + w2.z*s2 + w3.z*s3);
        v.w = AS*(w0.w*s0 + w1.w*s1 + w2.w*s2 + w3.w*s3);
        red4(dst + 32 + q*4, v);
    }
    // i3=4: out ch 48..55 ; weights w[24+c], w[88+c], w[168+c], w[248+c]
    #pragma unroll
    for (int q=0;q<2;q++){
        float4 w0=WL1(6+q), w1=WL1(22+q), w2=WL1(42+q), w3=WL1(62+q);
        float4 v;
        v.x = AS*(w0.x*s0 + w1.x*s1 + w2.x*s2 + w3.x*s3);
        v.y = AS*(w0.y*s0 + w1.y*s1 + w2.y*s2 + w3.y*s3);
        v.z = AS*(w0.z*s0 + w1.z*s1 + w2.z*s2 + w3.z*s3);
        v.w = AS*(w0.w*s0 + w1.w*s1 + w2.w*s2 + w3.w*s3);
        red4(dst + 48 + q*4, v);
    }
    // i3=6: out ch 64 + c*3 + k ; weights w[32+c],w[48+c],w[112+c],w[128+c],w[192+c],w[208+c]
    const float A6 = ALPHA_V6*INV_NN;
    #pragma unroll
    for (int q=0;q<4;q++){
        float4 wa=WL1(8+q), wb=WL1(12+q), wc=WL1(28+q), wd=WL1(32+q), we=WL1(48+q), wf=WL1(52+q);
        float fa[4]={wa.x,wa.y,wa.z,wa.w}, fb[4]={wb.x,wb.y,wb.z,wb.w};
        float fc[4]={wc.x,wc.y,wc.z,wc.w}, fd[4]={wd.x,wd.y,wd.z,wd.w};
        float fe[4]={we.x,we.y,we.z,we.w}, ff[4]={wf.x,wf.y,wf.z,wf.w};
        float o[12];
        #pragma unroll
        for (int cc=0;cc<4;cc++){
            #pragma unroll
            for (int k=0;k<3;k++)
                o[cc*3+k] = A6*(fa[cc]*c01[k] + fb[cc]*c10[k] + fc[cc]*c12[k]
                              + fd[cc]*c21[k] + fe[cc]*c23[k] + ff[cc]*c32[k]);
        }
        red4(dst + 64 + q*12 + 0, make_float4(o[0],o[1],o[2],o[3]));
        red4(dst + 64 + q*12 + 4, make_float4(o[4],o[5],o[6],o[7]));
        red4(dst + 64 + q*12 + 8, make_float4(o[8],o[9],o[10],o[11]));
    }
    // i3=7: out ch 112 + c*3 + k ; weights w[96+c], w[176+c], w[256+c] (alpha=1)
    #pragma unroll
    for (int q=0;q<4;q++){
        float4 wg=WL1(24+q), wh=WL1(44+q), wi=WL1(64+q);
        float fg[4]={wg.x,wg.y,wg.z,wg.w}, fh[4]={wh.x,wh.y,wh.z,wh.w}, fi[4]={wi.x,wi.y,wi.z,wi.w};
        float o[12];
        #pragma unroll
        for (int cc=0;cc<4;cc++){
            #pragma unroll
            for (int k=0;k<3;k++)
                o[cc*3+k] = INV_NN*(fg[cc]*c11[k] + fh[cc]*c22[k] + fi[cc]*c33[k]);
        }
        red4(dst + 112 + q*12 + 0, make_float4(o[0],o[1],o[2],o[3]));
        red4(dst + 112 + q*12 + 4, make_float4(o[4],o[5],o[6],o[7]));
        red4(dst + 112 + q*12 + 8, make_float4(o[8],o[9],o[10],o[11]));
    }
    #undef WL1
}

// ============================================================================
__global__ void gate_kernel(){
    int n = blockIdx.x*blockDim.x + threadIdx.x;
    if (n >= NN) return;
    const float* x = g_x1 + (size_t)n*160;
    float* o = g_gate + (size_t)n*128;
    #pragma unroll
    for (int c=0;c<16;c++){
        o[c]    = fmaxf(x[c], 0.f);
        o[16+c] = tanhf(x[16+c]);
    }
    float g[32];
    #pragma unroll
    for (int c=0;c<8;c++){
        g[c]    = fmaxf(x[32+c], 0.f);
        g[8+c]  = tanhf(x[40+c]);
        g[16+c] = fmaxf(x[48+c], 0.f);
        g[24+c] = tanhf(x[56+c]);
    }
    #pragma unroll
    for (int c=0;c<32;c++){
        float gv = g[c];
        o[32+c*3+0] = x[64+c*3+0]*gv;
        o[32+c*3+1] = x[64+c*3+1]*gv;
        o[32+c*3+2] = x[64+c*3+2]*gv;
    }
}

// ============================================================================
__global__ void tp2_kernel(const int* __restrict__ esrc, const int* __restrict__ edst){
    __shared__ float cg0;
    __shared__ float cg110[9];
    if (threadIdx.x == 0) cg0 = g_cg[OFF000];
    if (threadIdx.x < 9) cg110[threadIdx.x] = g_cg[OFF110 + threadIdx.x];
    __syncthreads();
    int e = blockIdx.x*blockDim.x + threadIdx.x;
    if (e >= NE) return;
    float dn = g_d[e];
    if (dn >= 3.2f) return;          // w2 == 0
    int s = esrc[e], d = edst[e];

    float xf = dn * ((float)(TBL-1)/3.2f);
    int i0 = (int)xf; if (i0 > TBL-2) i0 = TBL-2;
    float fr = xf - (float)i0;
    const float4* T0 = reinterpret_cast<const float4*>(g_tbl2 + (size_t)i0*32);
    const float4* T1 = reinterpret_cast<const float4*>(g_tbl2 + (size_t)(i0+1)*32);
    float w[32];
    #pragma unroll
    for (int q=0;q<8;q++){
        float4 v = lerp4(T0[q], T1[q], fr);
        w[q*4]=v.x; w[q*4+1]=v.y; w[q*4+2]=v.z; w[q*4+3]=v.w;
    }

    const float* x = g_gate + (size_t)s*128;
    float sh1[3];
    sh1[0]=g_sh[(size_t)e*16+1]; sh1[1]=g_sh[(size_t)e*16+2]; sh1[2]=g_sh[(size_t)e*16+3];
    float val = 0.f;
    #pragma unroll
    for (int u=0;u<16;u++) val += x[u]*w[u];
    val *= cg0;
    float v2 = 0.f;
    #pragma unroll
    for (int u=0;u<16;u++){
        const float* av = x + 32 + u*3;
        float t = 0.f;
        #pragma unroll
        for (int i=0;i<3;i++){
            #pragma unroll
            for (int j=0;j<3;j++) t += av[i]*sh1[j]*cg110[i*3+j];
        }
        v2 += w[16+u]*t;
    }
    val = (val + v2)*ALPHA_TP2*INV_NN;
    atomicAdd(g_nodeout + d, val);
}

// ============================================================================
__global__ void final_kernel(const int* __restrict__ batch, float* __restrict__ dout){
    int n = blockIdx.x*blockDim.x + threadIdx.x;
    if (n >= NN) return;
    atomicAdd(dout + batch[n], g_nodeout[n]*INV_SQRT_N);
}

// ============================================================================
extern "C" void kernel_launch(void* const* d_in, const int* in_sizes, int n_in,
                              void* d_out, int out_size){
    const float* pos     = (const float*)d_in[0];
    const float* w_fc1_1 = (const float*)d_in[1];
    const float* w_fc1_2 = (const float*)d_in[2];
    const float* w_fc2_1 = (const float*)d_in[3];
    const float* w_fc2_2 = (const float*)d_in[4];
    const int*   esrc    = (const int*)d_in[5];
    const int*   edst    = (const int*)d_in[6];
    const int*   batch   = (const int*)d_in[7];
    float* dout = (float*)d_out;

    cg_init_kernel<<<13, 128>>>();
    zero_kernel<<<(NN*160 + 255)/256, 256>>>(dout);
    edge_geom_kernel<<<NE/256, 256>>>(pos, esrc, edst);

    table_kernel<272><<<TBL/8, 256>>>(w_fc1_1, w_fc1_2);
    table_kernel<32> <<<TBL/8, 256>>>(w_fc2_1, w_fc2_2);

    tp1_kernel<<<NE/256, 256>>>(esrc, edst);
    gate_kernel<<<(NN + 255)/256, 256>>>();
    tp2_kernel<<<NE/256, 256>>>(esrc, edst);
    final_kernel<<<(NN + 255)/256, 256>>>(batch, dout);
}

// round 16
// speedup vs baseline: 7.9723x; 1.0723x over previous
#include <cuda_runtime.h>
#include <cuda_bf16.h>
#include <math.h>
#include <stdint.h>

#define NE 640000
#define NN 20000
#define NG 16
#define TBL 4096
#define NBIN 4096

// ---- device scratch (no allocations allowed) ----
__device__ float g_sh [(size_t)NE * 16];
__device__ float g_d  [(size_t)NE];
__device__ float g_x0 [(size_t)NN * 16];
__device__ float g_x1 [(size_t)NN * 160];
__device__ float g_gate[(size_t)NN * 128];
__device__ float g_nodeout[NN];
__device__ float g_cg[651];
__device__ float g_tbl1[(size_t)TBL * 272];
__device__ float g_tbl2[(size_t)TBL * 32];
__device__ int   g_hist[NBIN];
__device__ int   g_binoff[NBIN];
__device__ int   g_perm[NE];
__device__ float g_dsort[NE];

// CG table offsets, layout (i*d2+j)*d3+k
#define OFF000 0
#define OFF110 1
#define OFF220 10
#define OFF330 35
#define OFF011 84
#define OFF101 93
#define OFF111 102
#define OFF121 129
#define OFF211 174
#define OFF221 219
#define OFF231 294
#define OFF321 399
#define OFF331 504
#define CGTOT  651

#define INV_NN     0.17677669529663687f   // 1/sqrt(E/N)=1/sqrt(32)
#define FCH_SCALE  0.02795084971874737f   // sqrt(2/10)/16
#define ALPHA_S    0.5f
#define ALPHA_V6   0.7071067811865476f
#define ALPHA_TP2  0.17677669529663687f   // sqrt(1/32)
#define INV_SQRT_N 0.007071067811865475f  // 1/sqrt(20000)

#define SQ3f   1.7320508075688772f
#define SQ5f   2.23606797749979f
#define SQ7f   2.6457513110645907f
#define SQ15f  3.872983346207417f
#define SQ42f  6.48074069840786f
#define SQ70f  8.366600265340756f
#define SQ105f 10.246950765959598f
#define SQRT10f 3.1622776601683795f

// ---- vectorized global reduction (sm_90+) ----
__device__ __forceinline__ void red4(float* p, float4 v){
    asm volatile("red.global.add.v4.f32 [%0], {%1,%2,%3,%4};"
                 :: "l"(p), "f"(v.x), "f"(v.y), "f"(v.z), "f"(v.w) : "memory");
}

__device__ __forceinline__ float4 lerp4(float4 a, float4 b, float f){
    return make_float4(a.x + f*(b.x-a.x), a.y + f*(b.y-a.y),
                       a.z + f*(b.z-a.z), a.w + f*(b.w-a.w));
}

// ============================================================================
// CG init (mirrors reference exactly, fp64). One block per CG tensor.
// Max tensor size = 7*7*3 = 147.
// ============================================================================
#define CGMAX 147

__device__ double dfact(int n){ double r=1.0; for(int i=2;i<=n;i++) r*= (double)i; return r; }

__device__ double cg_complex_d(int j1,int m1,int j2,int m2,int j3,int m3){
    if (m1+m2 != m3) return 0.0;
    double pref = sqrt((2.0*j3+1.0)*dfact(j3+j1-j2)*dfact(j3-j1+j2)*dfact(j1+j2-j3)/dfact(j1+j2+j3+1));
    pref *= sqrt(dfact(j3+m3)*dfact(j3-m3)*dfact(j1-m1)*dfact(j1+m1)*dfact(j2-m2)*dfact(j2+m2));
    double s = 0.0;
    for (int k=0; k<=j1+j2-j3; k++){
        int e2=j1-m1-k, e3=j2+m2-k, e4=j3-j2+m1+k, e5=j3-j1-m2+k;
        if (e2<0||e3<0||e4<0||e5<0) continue;
        double den = dfact(k)*dfact(j1+j2-j3-k)*dfact(e2)*dfact(e3)*dfact(e4)*dfact(e5);
        s += ((k&1)? -1.0:1.0)/den;
    }
    return pref*s;
}

__device__ void build_U(int l, double* Ur, double* Ui){
    int d = 2*l+1;
    for (int i=0;i<d*d;i++){ Ur[i]=0.0; Ui[i]=0.0; }
    Ur[l*d+l] = 1.0;
    const double is2 = 0.70710678118654752440;
    for (int m=1;m<=l;m++){
        double sgn = (m&1)? -1.0:1.0;
        Ur[(l+m)*d+(l+m)] = sgn*is2;
        Ur[(l+m)*d+(l-m)] = is2;
        Ui[(l-m)*d+(l+m)] = -sgn*is2;
        Ui[(l-m)*d+(l-m)] = is2;
    }
}

__global__ void cg_init_kernel(){
    const int L1[13]  = {0,1,2,3,0,1,1,1,2,2,2,3,3};
    const int L2[13]  = {0,1,2,3,1,0,1,2,1,2,3,2,3};
    const int L3[13]  = {0,0,0,0,1,1,1,1,1,1,1,1,1};
    const int OFF[14] = {0,1,10,35,84,93,102,129,174,219,294,399,504,651};
    int combo = blockIdx.x;           // 0..12
    int l1=L1[combo], l2=L2[combo], l3=L3[combo];
    int d1=2*l1+1, d2=2*l2+1, d3=2*l3+1;
    int base = OFF[combo];
    int cnt = OFF[combo+1] - base;    // <= 147 (7*7*3)

    __shared__ double U1r[49],U1i[49],U2r[49],U2i[49],U3r[9],U3i[9];
    __shared__ double sC[CGMAX], sTr[CGMAX], sTi[CGMAX];
    int t = threadIdx.x;
    if (t == 0) build_U(l1, U1r, U1i);
    if (t == 1) build_U(l2, U2r, U2i);
    if (t == 2) build_U(l3, U3r, U3i);

    for (int r = t; r < cnt; r += blockDim.x){
        int c = r % d3, b = (r/d3) % d2, a = r/(d3*d2);
        sC[r] = cg_complex_d(l1, a-l1, l2, b-l2, l3, c-l3);
    }
    __syncthreads();

    for (int r = t; r < cnt; r += blockDim.x){
        int k = r % d3, j = (r/d3) % d2, i = r/(d3*d2);
        double tr = 0.0, ti = 0.0;
        for (int a=0; a<d1; a++){
            double r1=U1r[i*d1+a], i1=U1i[i*d1+a];
            if (r1==0.0 && i1==0.0) continue;
            for (int b=0; b<d2; b++){
                double r2=U2r[j*d2+b], i2=U2i[j*d2+b];
                if (r2==0.0 && i2==0.0) continue;
                double pr=r1*r2-i1*i2, pi=r1*i2+i1*r2;
                for (int c=0; c<d3; c++){
                    double cv = sC[(a*d2+b)*d3+c];
                    if (cv==0.0) continue;
                    double r3=U3r[k*d3+c], i3=U3i[k*d3+c];
                    tr += (pr*r3 + pi*i3)*cv;   // * conj(U3)
                    ti += (pi*r3 - pr*i3)*cv;
                }
            }
        }
        sTr[r]=tr; sTi[r]=ti;
    }
    __syncthreads();

    if (t == 0){
        double sa=0.0, sb=0.0;
        for (int q=0;q<cnt;q++){ sa += fabs(sTr[q]); sb += fabs(sTi[q]); }
        bool useR = (sa >= sb);
        double nrm = 0.0;
        for (int q=0;q<cnt;q++){ double v = useR? sTr[q]:sTi[q]; nrm += v*v; }
        double inv = 1.0/sqrt(nrm);
        for (int q=0;q<cnt;q++){ double v = useR? sTr[q]:sTi[q]; g_cg[base+q] = (float)(v*inv); }
    }
}

// ============================================================================
__global__ void zero_kernel(float* __restrict__ dout){
    int i = blockIdx.x*blockDim.x + threadIdx.x;
    if (i < NN*16)  g_x0[i] = 0.f;
    if (i < NN*160) g_x1[i] = 0.f;
    if (i < NN)     g_nodeout[i] = 0.f;
    if (i < NG)     dout[i] = 0.f;
    if (i < NBIN)   g_hist[i] = 0;
}

// ============================================================================
// edge geometry: d, sh; scatter sh into x0[dst]; histogram d-bin
// ============================================================================
__global__ void edge_geom_kernel(const float* __restrict__ pos,
                                 const int* __restrict__ esrc,
                                 const int* __restrict__ edst){
    int e = blockIdx.x*blockDim.x + threadIdx.x;
    if (e >= NE) return;
    int s = esrc[e], d = edst[e];
    float ex = pos[d*3+0]-pos[s*3+0];
    float ey = pos[d*3+1]-pos[s*3+1];
    float ez = pos[d*3+2]-pos[s*3+2];
    float dn = sqrtf(ex*ex+ey*ey+ez*ez + 1e-12f);
    float inv = 1.f/dn;
    float x = ex*inv, y = ey*inv, z = ez*inv;
    float xx=x*x, yy=y*y, zz=z*z;
    float sh[16];
    sh[0]=1.f;
    sh[1]=SQ3f*y; sh[2]=SQ3f*z; sh[3]=SQ3f*x;
    sh[4]=SQ15f*x*y; sh[5]=SQ15f*y*z; sh[6]=0.5f*SQ5f*(3.f*zz-1.f);
    sh[7]=SQ15f*x*z; sh[8]=0.5f*SQ15f*(xx-yy);
    sh[9] =0.25f*SQ70f*y*(3.f*xx-yy);
    sh[10]=SQ105f*x*y*z;
    sh[11]=0.25f*SQ42f*y*(5.f*zz-1.f);
    sh[12]=0.5f*SQ7f*z*(5.f*zz-3.f);
    sh[13]=0.25f*SQ42f*x*(5.f*zz-1.f);
    sh[14]=0.5f*SQ105f*z*(xx-yy);
    sh[15]=0.25f*SQ70f*x*(xx-3.f*yy);

    float4* shp = reinterpret_cast<float4*>(g_sh + (size_t)e*16);
    shp[0]=make_float4(sh[0],sh[1],sh[2],sh[3]);
    shp[1]=make_float4(sh[4],sh[5],sh[6],sh[7]);
    shp[2]=make_float4(sh[8],sh[9],sh[10],sh[11]);
    shp[3]=make_float4(sh[12],sh[13],sh[14],sh[15]);

    g_d[e] = dn;
    int bin = (int)(dn * ((float)NBIN/3.2f));
    if (bin > NBIN-1) bin = NBIN-1;
    atomicAdd(&g_hist[bin], 1);

    float* x0 = g_x0 + (size_t)d*16;
    red4(x0+0,  make_float4(sh[0]*INV_NN, sh[1]*INV_NN, sh[2]*INV_NN, sh[3]*INV_NN));
    red4(x0+4,  make_float4(sh[4]*INV_NN, sh[5]*INV_NN, sh[6]*INV_NN, sh[7]*INV_NN));
    red4(x0+8,  make_float4(sh[8]*INV_NN, sh[9]*INV_NN, sh[10]*INV_NN, sh[11]*INV_NN));
    red4(x0+12, make_float4(sh[12]*INV_NN, sh[13]*INV_NN, sh[14]*INV_NN, sh[15]*INV_NN));
}

// ============================================================================
// scan over NBIN histogram -> exclusive offsets (single block, 1024 threads)
// ============================================================================
__global__ void scan_kernel(){
    __shared__ int s[NBIN];
    __shared__ int part[1024];
    int t = threadIdx.x;
    for (int i=t; i<NBIN; i+=1024) s[i] = g_hist[i];
    __syncthreads();
    int base = t*4;
    int a0=s[base], a1=s[base+1], a2=s[base+2], a3=s[base+3];
    int tot = a0+a1+a2+a3;
    part[t] = tot;
    __syncthreads();
    for (int off=1; off<1024; off<<=1){
        int v = (t >= off) ? part[t-off] : 0;
        __syncthreads();
        part[t] += v;
        __syncthreads();
    }
    int excl = part[t] - tot;
    g_binoff[base+0] = excl;
    g_binoff[base+1] = excl + a0;
    g_binoff[base+2] = excl + a0 + a1;
    g_binoff[base+3] = excl + a0 + a1 + a2;
}

// ============================================================================
// scatter: counting-sort edges by d-bin -> g_perm, g_dsort
// ============================================================================
__global__ void scatter_kernel(){
    int e = blockIdx.x*blockDim.x + threadIdx.x;
    if (e >= NE) return;
    float dn = g_d[e];
    int bin = (int)(dn * ((float)NBIN/3.2f));
    if (bin > NBIN-1) bin = NBIN-1;
    int idx = atomicAdd(&g_binoff[bin], 1);
    g_perm[idx] = e;
    g_dsort[idx] = dn;
}

// ============================================================================
// table build: w(d) on TBL-point grid over [0, 3.2]. 8 rows/block.
// ============================================================================
template<int NOUT>
__global__ void table_kernel(const float* __restrict__ Wa,
                             const float* __restrict__ Wb){
    float* tbl = (NOUT == 272) ? g_tbl1 : g_tbl2;
    __shared__ float semb[8][10];
    __shared__ float hh[8][256];      // [row][hidden j]
    int r0 = blockIdx.x*8;
    int t = threadIdx.x;
    const float stepw = 3.2f/11.f;
    const float dgrid = 3.2f/(float)(TBL-1);
    if (t < 80){
        int rr = t/10, k = t%10;
        float dv = (float)(r0+rr)*dgrid;
        float c = (float)(k+1)*stepw;
        float u = (dv-c)/stepw;
        float u2 = u*u;
        float f = 0.f;
        if (u2 < 1.f){
            float den = fmaxf(1.f-u2, 1e-6f);
            f = 1.14136f*expf(-u2/den)*SQRT10f;
        }
        semb[rr][k] = f;
    }
    __syncthreads();
    {
        float w[10];
        #pragma unroll
        for (int k=0;k<10;k++) w[k] = Wa[k*256 + t];
        #pragma unroll
        for (int rr=0; rr<8; rr++){
            float acc = 0.f;
            #pragma unroll
            for (int k=0;k<10;k++) acc += semb[rr][k]*w[k];
            hh[rr][t] = fmaxf(acc, 0.f)*FCH_SCALE;
        }
    }
    __syncthreads();
    if (NOUT == 272){
        for (int k=t; k<NOUT; k+=256){
            float acc[8];
            #pragma unroll
            for (int r=0;r<8;r++) acc[r] = 0.f;
            for (int j=0;j<256;j++){
                float wv = Wb[j*NOUT + k];
                #pragma unroll
                for (int r=0;r<8;r++) acc[r] += hh[r][j]*wv;
            }
            #pragma unroll
            for (int r=0;r<8;r++) tbl[(size_t)(r0+r)*NOUT + k] = acc[r];
        }
    } else {
        int k  = t & 31;
        int rr = t >> 5;          // 0..7
        float acc = 0.f;
        for (int j=0;j<256;j++) acc += hh[rr][j]*Wb[j*NOUT + k];
        tbl[(size_t)(r0+rr)*NOUT + k] = acc;
    }
}

// ============================================================================
// TP1 (d-sorted order): weights lerped from table (warp-shared rows),
// scatter into g_x1[dst]
// ============================================================================
template<int D1,int D2>
__device__ __forceinline__ void contr3(const float* a, const float* b,
                                       const float* cgt, float* o){
    o[0]=0.f; o[1]=0.f; o[2]=0.f;
    #pragma unroll
    for (int i=0;i<D1;i++){
        #pragma unroll
        for (int j=0;j<D2;j++){
            float p = a[i]*b[j];
            const float* c = cgt + (i*D2+j)*3;
            o[0] += p*c[0]; o[1] += p*c[1]; o[2] += p*c[2];
        }
    }
}

__global__ void tp1_kernel(const int* __restrict__ esrc, const int* __restrict__ edst){
    __shared__ float cg[CGTOT];
    for (int i=threadIdx.x; i<CGTOT; i+=blockDim.x) cg[i] = g_cg[i];
    __syncthreads();
    int i = blockIdx.x*blockDim.x + threadIdx.x;
    if (i >= NE) return;
    float dn = g_dsort[i];
    if (dn >= 3.2f) return;          // all radial bases vanish -> w == 0
    int e = g_perm[i];
    int s = esrc[e], d = edst[e];

    float xf = dn * ((float)(TBL-1)/3.2f);
    int i0 = (int)xf; if (i0 > TBL-2) i0 = TBL-2;
    float fr = xf - (float)i0;
    const float4* T0 = reinterpret_cast<const float4*>(g_tbl1 + (size_t)i0*272);
    const float4* T1 = reinterpret_cast<const float4*>(g_tbl1 + (size_t)(i0+1)*272);
    #define WL1(slot) lerp4(__ldg(T0+(slot)), __ldg(T1+(slot)), fr)

    float a[16], b[16];
    const float4* xp = reinterpret_cast<const float4*>(g_x0 + (size_t)s*16);
    #pragma unroll
    for (int q=0;q<4;q++){ float4 v = xp[q]; a[q*4]=v.x; a[q*4+1]=v.y; a[q*4+2]=v.z; a[q*4+3]=v.w; }
    const float4* shp = reinterpret_cast<const float4*>(g_sh + (size_t)e*16);
    #pragma unroll
    for (int q=0;q<4;q++){ float4 v = shp[q]; b[q*4]=v.x; b[q*4+1]=v.y; b[q*4+2]=v.z; b[q*4+3]=v.w; }

    // scalar contractions (l,l,0)
    float s0 = a[0]*b[0]*cg[OFF000];
    float s1 = 0.f;
    #pragma unroll
    for (int i1=0;i1<3;i1++){ float ai=a[1+i1];
        #pragma unroll
        for (int j=0;j<3;j++) s1 += ai*b[1+j]*cg[OFF110+i1*3+j]; }
    float s2 = 0.f;
    #pragma unroll
    for (int i1=0;i1<5;i1++){ float ai=a[4+i1];
        #pragma unroll
        for (int j=0;j<5;j++) s2 += ai*b[4+j]*cg[OFF220+i1*5+j]; }
    float s3 = 0.f;
    #pragma unroll
    for (int i1=0;i1<7;i1++){ float ai=a[9+i1];
        #pragma unroll
        for (int j=0;j<7;j++) s3 += ai*b[9+j]*cg[OFF330+i1*7+j]; }

    // vector contractions (l1,l2,1)
    float c01[3],c10[3],c12[3],c21[3],c23[3],c32[3],c11[3],c22[3],c33[3];
    contr3<1,3>(a+0, b+1, cg+OFF011, c01);
    contr3<3,1>(a+1, b+0, cg+OFF101, c10);
    contr3<3,5>(a+1, b+4, cg+OFF121, c12);
    contr3<5,3>(a+4, b+1, cg+OFF211, c21);
    contr3<5,7>(a+4, b+9, cg+OFF231, c23);
    contr3<7,5>(a+9, b+4, cg+OFF321, c32);
    contr3<3,3>(a+1, b+1, cg+OFF111, c11);
    contr3<5,5>(a+4, b+4, cg+OFF221, c22);
    contr3<7,7>(a+9, b+9, cg+OFF331, c33);

    float* dst = g_x1 + (size_t)d*160;
    const float AS = ALPHA_S*INV_NN;

    // i3=0: out ch 0..15 ; weights w[c], w[64+c], w[144+c], w[224+c]
    #pragma unroll
    for (int q=0;q<4;q++){
        float4 w0=WL1(0+q), w1=WL1(16+q), w2=WL1(36+q), w3=WL1(56+q);
        float4 v;
        v.x = AS*(w0.x*s0 + w1.x*s1 + w2.x*s2 + w3.x*s3);
        v.y = AS*(w0.y*s0 + w1.y*s1 + w2.y*s2 + w3.y*s3);
        v.z = AS*(w0.z*s0 + w1.z*s1 + w2.z*s2 + w3.z*s3);
        v.w = AS*(w0.w*s0 + w1.w*s1 + w2.w*s2 + w3.w*s3);
        red4(dst + q*4, v);
    }
    // i3=2: out ch 32..39
    #pragma unroll
    for (int q=0;q<2;q++){
        float4 w0=WL1(4+q), w1=WL1(20+q), w2=WL1(40+q), w3=WL1(60+q);
        float4 v;
        v.x = AS*(w0.x*s0 + w1.x*s1 + w2.x*s2 + w3.x*s3);
        v.y = AS*(w0.y*s0 + w1.y*s1 + w2.y*s2 + w3.y*s3);
        v.z = AS*(w0.z*s0 + w1.z*s1 + w2.z*s2 + w3.z*s3);
        v.w = AS*(w0.w*s0 + w1.w*s1 + w2.w*s2 + w3.w*s3);
        red4(dst + 32 + q*4, v);
    }
    // i3=4: out ch 48..55
    #pragma unroll
    for (int q=0;q<2;q++){
        float4 w0=WL1(6+q), w1=WL1(22+q), w2=WL1(42+q), w3=WL1(62+q);
        float4 v;
        v.x = AS*(w0.x*s0 + w1.x*s1 + w2.x*s2 + w3.x*s3);
        v.y = AS*(w0.y*s0 + w1.y*s1 + w2.y*s2 + w3.y*s3);
        v.z = AS*(w0.z*s0 + w1.z*s1 + w2.z*s2 + w3.z*s3);
        v.w = AS*(w0.w*s0 + w1.w*s1 + w2.w*s2 + w3.w*s3);
        red4(dst + 48 + q*4, v);
    }
    // i3=6: out ch 64 + c*3 + k
    const float A6 = ALPHA_V6*INV_NN;
    #pragma unroll
    for (int q=0;q<4;q++){
        float4 wa=WL1(8+q), wb=WL1(12+q), wc=WL1(28+q), wd=WL1(32+q), we=WL1(48+q), wf=WL1(52+q);
        float fa[4]={wa.x,wa.y,wa.z,wa.w}, fb[4]={wb.x,wb.y,wb.z,wb.w};
        float fc[4]={wc.x,wc.y,wc.z,wc.w}, fd[4]={wd.x,wd.y,wd.z,wd.w};
        float fe[4]={we.x,we.y,we.z,we.w}, ff[4]={wf.x,wf.y,wf.z,wf.w};
        float o[12];
        #pragma unroll
        for (int cc=0;cc<4;cc++){
            #pragma unroll
            for (int k=0;k<3;k++)
                o[cc*3+k] = A6*(fa[cc]*c01[k] + fb[cc]*c10[k] + fc[cc]*c12[k]
                              + fd[cc]*c21[k] + fe[cc]*c23[k] + ff[cc]*c32[k]);
        }
        red4(dst + 64 + q*12 + 0, make_float4(o[0],o[1],o[2],o[3]));
        red4(dst + 64 + q*12 + 4, make_float4(o[4],o[5],o[6],o[7]));
        red4(dst + 64 + q*12 + 8, make_float4(o[8],o[9],o[10],o[11]));
    }
    // i3=7: out ch 112 + c*3 + k (alpha=1)
    #pragma unroll
    for (int q=0;q<4;q++){
        float4 wg=WL1(24+q), wh=WL1(44+q), wi=WL1(64+q);
        float fg[4]={wg.x,wg.y,wg.z,wg.w}, fh[4]={wh.x,wh.y,wh.z,wh.w}, fi[4]={wi.x,wi.y,wi.z,wi.w};
        float o[12];
        #pragma unroll
        for (int cc=0;cc<4;cc++){
            #pragma unroll
            for (int k=0;k<3;k++)
                o[cc*3+k] = INV_NN*(fg[cc]*c11[k] + fh[cc]*c22[k] + fi[cc]*c33[k]);
        }
        red4(dst + 112 + q*12 + 0, make_float4(o[0],o[1],o[2],o[3]));
        red4(dst + 112 + q*12 + 4, make_float4(o[4],o[5],o[6],o[7]));
        red4(dst + 112 + q*12 + 8, make_float4(o[8],o[9],o[10],o[11]));
    }
    #undef WL1
}

// ============================================================================
__global__ void gate_kernel(){
    int n = blockIdx.x*blockDim.x + threadIdx.x;
    if (n >= NN) return;
    const float* x = g_x1 + (size_t)n*160;
    float* o = g_gate + (size_t)n*128;
    #pragma unroll
    for (int c=0;c<16;c++){
        o[c]    = fmaxf(x[c], 0.f);
        o[16+c] = tanhf(x[16+c]);
    }
    float g[32];
    #pragma unroll
    for (int c=0;c<8;c++){
        g[c]    = fmaxf(x[32+c], 0.f);
        g[8+c]  = tanhf(x[40+c]);
        g[16+c] = fmaxf(x[48+c], 0.f);
        g[24+c] = tanhf(x[56+c]);
    }
    #pragma unroll
    for (int c=0;c<32;c++){
        float gv = g[c];
        o[32+c*3+0] = x[64+c*3+0]*gv;
        o[32+c*3+1] = x[64+c*3+1]*gv;
        o[32+c*3+2] = x[64+c*3+2]*gv;
    }
}

// ============================================================================
__global__ void tp2_kernel(const int* __restrict__ esrc, const int* __restrict__ edst){
    __shared__ float cg0;
    __shared__ float cg110[9];
    if (threadIdx.x == 0) cg0 = g_cg[OFF000];
    if (threadIdx.x < 9) cg110[threadIdx.x] = g_cg[OFF110 + threadIdx.x];
    __syncthreads();
    int i = blockIdx.x*blockDim.x + threadIdx.x;
    if (i >= NE) return;
    float dn = g_dsort[i];
    if (dn >= 3.2f) return;          // w2 == 0
    int e = g_perm[i];
    int s = esrc[e], d = edst[e];

    float xf = dn * ((float)(TBL-1)/3.2f);
    int i0 = (int)xf; if (i0 > TBL-2) i0 = TBL-2;
    float fr = xf - (float)i0;
    const float4* T0 = reinterpret_cast<const float4*>(g_tbl2 + (size_t)i0*32);
    const float4* T1 = reinterpret_cast<const float4*>(g_tbl2 + (size_t)(i0+1)*32);
    float w[32];
    #pragma unroll
    for (int q=0;q<8;q++){
        float4 v = lerp4(__ldg(T0+q), __ldg(T1+q), fr);
        w[q*4]=v.x; w[q*4+1]=v.y; w[q*4+2]=v.z; w[q*4+3]=v.w;
    }

    const float* x = g_gate + (size_t)s*128;
    float sh1[3];
    sh1[0]=g_sh[(size_t)e*16+1]; sh1[1]=g_sh[(size_t)e*16+2]; sh1[2]=g_sh[(size_t)e*16+3];
    float val = 0.f;
    #pragma unroll
    for (int u=0;u<16;u++) val += x[u]*w[u];
    val *= cg0;
    float v2 = 0.f;
    #pragma unroll
    for (int u=0;u<16;u++){
        const float* av = x + 32 + u*3;
        float t = 0.f;
        #pragma unroll
        for (int i1=0;i1<3;i1++){
            #pragma unroll
            for (int j=0;j<3;j++) t += av[i1]*sh1[j]*cg110[i1*3+j];
        }
        v2 += w[16+u]*t;
    }
    val = (val + v2)*ALPHA_TP2*INV_NN;
    atomicAdd(g_nodeout + d, val);
}

// ============================================================================
__global__ void final_kernel(const int* __restrict__ batch, float* __restrict__ dout){
    int n = blockIdx.x*blockDim.x + threadIdx.x;
    if (n >= NN) return;
    atomicAdd(dout + batch[n], g_nodeout[n]*INV_SQRT_N);
}

// ============================================================================
extern "C" void kernel_launch(void* const* d_in, const int* in_sizes, int n_in,
                              void* d_out, int out_size){
    const float* pos     = (const float*)d_in[0];
    const float* w_fc1_1 = (const float*)d_in[1];
    const float* w_fc1_2 = (const float*)d_in[2];
    const float* w_fc2_1 = (const float*)d_in[3];
    const float* w_fc2_2 = (const float*)d_in[4];
    const int*   esrc    = (const int*)d_in[5];
    const int*   edst    = (const int*)d_in[6];
    const int*   batch   = (const int*)d_in[7];
    float* dout = (float*)d_out;

    cg_init_kernel<<<13, 128>>>();
    zero_kernel<<<(NN*160 + 255)/256, 256>>>(dout);
    edge_geom_kernel<<<NE/256, 256>>>(pos, esrc, edst);
    scan_kernel<<<1, 1024>>>();
    scatter_kernel<<<NE/256, 256>>>();

    table_kernel<272><<<TBL/8, 256>>>(w_fc1_1, w_fc1_2);
    table_kernel<32> <<<TBL/8, 256>>>(w_fc2_1, w_fc2_2);

    tp1_kernel<<<NE/256, 256>>>(esrc, edst);
    gate_kernel<<<(NN + 255)/256, 256>>>();
    tp2_kernel<<<NE/256, 256>>>(esrc, edst);
    final_kernel<<<(NN + 255)/256, 256>>>(batch, dout);
}